// round 1
// baseline (speedup 1.0000x reference)
#include <cuda_runtime.h>

#define LSN 4096   // layer size
#define NIN 1024   // input length (x columns)
#define BATN 64    // batch
#define FCN 512    // fc slice
#define NCLS 10

#define KCH1 8
#define KC1 128    // KCH1*KC1 = 1024
#define KCH2 16
#define KC2 256    // KCH2*KC2 = 4096

// ---------------- static scratch (no allocations allowed) ----------------
// g_d rows: 0=da1 1=1/da1 2=db1 3=1/db1 4=da2 5=1/da2 6=db2 7=1/db2
__device__ float g_d[8][LSN];
__device__ float g_buf1[NIN * LSN];        // A1^T then (in-place) C1^T : 1024 x 4096 (rows=k, cols=j)
__device__ float g_buf2[FCN * LSN];        // A2 then (in-place) C2     : 512  x 4096 (rows=j, cols=k)
__device__ float g_z1[BATN * NIN];         // x * db1
__device__ float g_z2[BATN * LSN];         // relu(layer1)+scaled by db2
__device__ float g_h2[BATN * FCN];         // relu(layer2)[:, :512]
__device__ float g_y1p[KCH1 * BATN * LSN]; // K-split partials layer 1
__device__ float g_y2p[KCH2 * BATN * FCN]; // K-split partials layer 2

// ---------------- cumulative products (d = [1, cumprod(subd)]) ----------------
__global__ void scan_kernel(const float* __restrict__ sa1, const float* __restrict__ sb1,
                            const float* __restrict__ sa2, const float* __restrict__ sb2) {
    const float* s;
    int w = blockIdx.x;
    if (w == 0) s = sa1; else if (w == 1) s = sb1; else if (w == 2) s = sa2; else s = sb2;
    float* d  = g_d[2 * w];
    float* di = g_d[2 * w + 1];
    __shared__ float sh[1024];
    int t = threadIdx.x;
    int base = 4 * t;
    float v0 = (base + 0 < LSN - 1) ? s[base + 0] : 1.f;
    float v1 = (base + 1 < LSN - 1) ? s[base + 1] : 1.f;
    float v2 = (base + 2 < LSN - 1) ? s[base + 2] : 1.f;
    float v3 = (base + 3 < LSN - 1) ? s[base + 3] : 1.f;
    sh[t] = v0 * v1 * v2 * v3;
    __syncthreads();
    for (int off = 1; off < 1024; off <<= 1) {
        float val = sh[t];
        if (t >= off) val *= sh[t - off];
        __syncthreads();
        sh[t] = val;
        __syncthreads();
    }
    float E = (t == 0) ? 1.f : sh[t - 1];
    float p0 = E, p1 = p0 * v0, p2 = p1 * v1, p3 = p2 * v2;
    d[base + 0] = p0; d[base + 1] = p1; d[base + 2] = p2; d[base + 3] = p3;
    di[base + 0] = 1.f / p0; di[base + 1] = 1.f / p1;
    di[base + 2] = 1.f / p2; di[base + 3] = 1.f / p3;
}

// ---------------- z1 = x * db1 ----------------
__global__ void z1prep_kernel(const float* __restrict__ x) {
    int idx = blockIdx.x * blockDim.x + threadIdx.x;   // 64*1024
    int k = idx & (NIN - 1);
    g_z1[idx] = x[idx] * g_d[2][k];
}

// ---------------- rank-K outer-product GEMM with diagonal rescale epilogue ----------------
// out[r, c] = (1/dR[r]) * (1/dC[c]) * sum_i P[i, r] * Q[i, c]   (P,Q rows have stride LSN)
template<int RR, int KD, int IR, int IC, int OB>
__global__ void gemmA_kernel(const float* __restrict__ P, const float* __restrict__ Q) {
    float* out = OB ? g_buf2 : g_buf1;
    __shared__ float shP[16][64];
    __shared__ float shQ[16][64];
    int r0 = blockIdx.y * 64, c0 = blockIdx.x * 64;
    int tid = threadIdx.x;
    int tx = tid & 15, ty = tid >> 4;
    float acc[4][4] = {};
    for (int i0 = 0; i0 < KD; i0 += 16) {
        #pragma unroll
        for (int it = 0; it < 4; ++it) {
            int e = it * 256 + tid;
            int kk = e >> 6, rc = e & 63;
            shP[kk][rc] = P[(i0 + kk) * LSN + r0 + rc];
            shQ[kk][rc] = Q[(i0 + kk) * LSN + c0 + rc];
        }
        __syncthreads();
        #pragma unroll
        for (int kk = 0; kk < 16; ++kk) {
            float a[4], b[4];
            #pragma unroll
            for (int u = 0; u < 4; ++u) a[u] = shP[kk][ty * 4 + u];
            #pragma unroll
            for (int v = 0; v < 4; ++v) b[v] = shQ[kk][tx * 4 + v];
            #pragma unroll
            for (int u = 0; u < 4; ++u)
                #pragma unroll
                for (int v = 0; v < 4; ++v) acc[u][v] += a[u] * b[v];
        }
        __syncthreads();
    }
    #pragma unroll
    for (int u = 0; u < 4; ++u) {
        int r = r0 + ty * 4 + u;
        float ir = g_d[IR][r];
        #pragma unroll
        for (int v = 0; v < 4; ++v) {
            int c = c0 + tx * 4 + v;
            out[r * LSN + c] = ir * g_d[IC][c] * acc[u][v];
        }
    }
}

// ---------------- in-place diagonal cumulative sum: C[r,c] = C[r-1,c-1] + A[r,c] ----------------
__global__ void diagscan_kernel(int which, int R) {
    float* buf = which ? g_buf2 : g_buf1;
    int t = blockIdx.x * blockDim.x + threadIdx.x;
    int total = R + LSN - 1;
    if (t >= total) return;
    int r0, c0;
    if (t < LSN) { r0 = 0; c0 = t; } else { r0 = t - LSN + 1; c0 = 0; }
    int len = (R - r0 < LSN - c0) ? (R - r0) : (LSN - c0);
    int idx = r0 * LSN + c0;
    float acc = 0.f;
    #pragma unroll 4
    for (int s = 0; s < len; ++s) {
        acc += buf[idx];
        buf[idx] = acc;
        idx += LSN + 1;
    }
}

// ---------------- apply GEMM: OUT(64 x N) = A(64 x KT) @ B, K-split into partials ----------------
template<int LAYER>
__global__ void gemm64_kernel() {
    constexpr int N  = (LAYER == 1) ? LSN : FCN;
    constexpr int KT = (LAYER == 1) ? NIN : LSN;
    constexpr int KC = (LAYER == 1) ? KC1 : KC2;
    constexpr int BT = (LAYER == 1) ? 0 : 1;     // BT=1: B stored as (N rows x KT cols)
    const float* A = (LAYER == 1) ? g_z1 : g_z2;
    const float* B = (LAYER == 1) ? g_buf1 : g_buf2;
    float* O = (LAYER == 1) ? g_y1p : g_y2p;
    __shared__ float shA[64][33];
    __shared__ float shB[32][65];
    int j0 = blockIdx.x * 64;
    int k0 = blockIdx.y * KC;
    int tid = threadIdx.x;
    int tx = tid & 15, ty = tid >> 4;
    float acc[4][4] = {};
    for (int ks = 0; ks < KC; ks += 32) {
        int kb = k0 + ks;
        #pragma unroll
        for (int it = 0; it < 8; ++it) {
            int e = it * 256 + tid;
            int bb = e >> 5, kk = e & 31;
            shA[bb][kk] = A[bb * KT + kb + kk];
        }
        if (BT == 0) {
            #pragma unroll
            for (int it = 0; it < 8; ++it) {
                int e = it * 256 + tid;
                int kk = e >> 6, jj = e & 63;
                shB[kk][jj] = B[(kb + kk) * N + j0 + jj];
            }
        } else {
            #pragma unroll
            for (int it = 0; it < 8; ++it) {
                int e = it * 256 + tid;
                int jj = e >> 5, kk = e & 31;
                shB[kk][jj] = B[(j0 + jj) * KT + kb + kk];
            }
        }
        __syncthreads();
        #pragma unroll
        for (int kk = 0; kk < 32; ++kk) {
            float a[4], b[4];
            #pragma unroll
            for (int u = 0; u < 4; ++u) a[u] = shA[ty * 4 + u][kk];
            #pragma unroll
            for (int v = 0; v < 4; ++v) b[v] = shB[kk][tx * 4 + v];
            #pragma unroll
            for (int u = 0; u < 4; ++u)
                #pragma unroll
                for (int v = 0; v < 4; ++v) acc[u][v] += a[u] * b[v];
        }
        __syncthreads();
    }
    #pragma unroll
    for (int u = 0; u < 4; ++u) {
        int bb = ty * 4 + u;
        #pragma unroll
        for (int v = 0; v < 4; ++v) {
            int j = j0 + tx * 4 + v;
            O[blockIdx.y * (64 * N) + bb * N + j] = acc[u][v];
        }
    }
}

// ---------------- reduce K-split partials + layer epilogues ----------------
__global__ void reduce1_kernel(const float* __restrict__ bias1) {
    int idx = blockIdx.x * blockDim.x + threadIdx.x;   // 64*4096
    int b = idx >> 12, j = idx & (LSN - 1);
    float s = 0.f;
    #pragma unroll
    for (int c = 0; c < KCH1; ++c) s += g_y1p[c * (BATN * LSN) + b * LSN + j];
    float h = g_d[0][j] * s + bias1[j];
    h = h > 0.f ? h : 0.f;
    g_z2[b * LSN + j] = h * g_d[6][j];
}

__global__ void reduce2_kernel(const float* __restrict__ bias2) {
    int idx = blockIdx.x * blockDim.x + threadIdx.x;   // 64*512
    int b = idx >> 9, j = idx & (FCN - 1);
    float s = 0.f;
    #pragma unroll
    for (int c = 0; c < KCH2; ++c) s += g_y2p[c * (BATN * FCN) + b * FCN + j];
    float h = g_d[4][j] * s + bias2[j];
    g_h2[b * FCN + j] = h > 0.f ? h : 0.f;
}

// ---------------- logits: warp per (b, c) ----------------
__global__ void logits_kernel(const float* __restrict__ W, const float* __restrict__ bl,
                              float* __restrict__ out) {
    int warp = (blockIdx.x * blockDim.x + threadIdx.x) >> 5;
    int lane = threadIdx.x & 31;
    if (warp >= BATN * NCLS) return;
    int b = warp / NCLS, c = warp % NCLS;
    const float* hrow = g_h2 + b * FCN;
    const float* wrow = W + c * FCN;
    float s = 0.f;
    for (int j = lane; j < FCN; j += 32) s += hrow[j] * wrow[j];
    #pragma unroll
    for (int off = 16; off; off >>= 1) s += __shfl_xor_sync(0xffffffffu, s, off);
    if (lane == 0) out[b * NCLS + c] = s + bl[c];
}

// ---------------- launch ----------------
extern "C" void kernel_launch(void* const* d_in, const int* in_sizes, int n_in,
                              void* d_out, int out_size) {
    (void)in_sizes; (void)n_in; (void)out_size;
    const float* x      = (const float*)d_in[0];
    const float* G1     = (const float*)d_in[1];
    const float* H1     = (const float*)d_in[2];
    const float* sA1    = (const float*)d_in[3];
    const float* sB1    = (const float*)d_in[4];
    const float* bias1  = (const float*)d_in[5];
    const float* G2     = (const float*)d_in[6];
    const float* H2     = (const float*)d_in[7];
    const float* sA2    = (const float*)d_in[8];
    const float* sB2    = (const float*)d_in[9];
    const float* bias2  = (const float*)d_in[10];
    const float* W      = (const float*)d_in[11];
    const float* bl     = (const float*)d_in[12];
    float* out = (float*)d_out;

    // cumprods + reciprocals
    scan_kernel<<<4, 1024>>>(sA1, sB1, sA2, sB2);
    // z1 = x * db1
    z1prep_kernel<<<(BATN * NIN) / 256, 256>>>(x);
    // A1^T (1024 x 4096): rows k scaled 1/db1, cols j scaled 1/da1, rank 48
    gemmA_kernel<NIN, 48, 3, 1, 0><<<dim3(LSN / 64, NIN / 64), 256>>>(H1, G1);
    // C1^T in place (diagonal cumsum)
    diagscan_kernel<<<(NIN + LSN - 1 + 255) / 256, 256>>>(0, NIN);
    // Y1 partials: z1(64x1024) @ C1^T(1024x4096), K split into 8
    gemm64_kernel<1><<<dim3(LSN / 64, KCH1), 256>>>();
    // z2 = relu(da1*Y1 + bias1) * db2
    reduce1_kernel<<<(BATN * LSN) / 256, 256>>>(bias1);
    // A2 (512 x 4096): rows j scaled 1/da2, cols k scaled 1/db2, rank 16
    gemmA_kernel<FCN, 16, 5, 7, 1><<<dim3(LSN / 64, FCN / 64), 256>>>(G2, H2);
    // C2 in place
    diagscan_kernel<<<(FCN + LSN - 1 + 255) / 256, 256>>>(1, FCN);
    // Y2 partials: z2(64x4096) @ C2^T(4096x512), K split into 16
    gemm64_kernel<2><<<dim3(FCN / 64, KCH2), 256>>>();
    // h2 = relu(da2*Y2 + bias2)
    reduce2_kernel<<<(BATN * FCN) / 256, 256>>>(bias2);
    // logits
    logits_kernel<<<(BATN * NCLS * 32 + 255) / 256, 256>>>(W, bl, out);
}

// round 2
// speedup vs baseline: 3.9446x; 3.9446x over previous
#include <cuda_runtime.h>

#define LSN 4096   // layer size
#define NIN 1024   // input length (x columns)
#define BATN 64    // batch
#define FCN 512    // fc slice
#define NCLS 10

#define KCH1 8
#define KC1 128    // KCH1*KC1 = 1024
#define KCH2 16
#define KC2 256    // KCH2*KC2 = 4096

#define DCH 64           // diag-scan chunk height
#define DMAX 5120        // >= LSN + NIN - 1
#define NCHMAX 16

// ---------------- static scratch (no allocations allowed) ----------------
// g_d rows: 0=da1 1=1/da1 2=db1 3=1/db1 4=da2 5=1/da2 6=db2 7=1/db2
__device__ float g_d[8][LSN];
__device__ float g_buf1[NIN * LSN];        // A1^T then (in-place) C1^T : 1024 x 4096 (rows=k, cols=j)
__device__ float g_buf2[FCN * LSN];        // A2 then (in-place) C2     : 512  x 4096 (rows=j, cols=k)
__device__ float g_z1[BATN * NIN];         // x * db1
__device__ float g_z2[BATN * LSN];         // relu(layer1) scaled by db2
__device__ float g_h2[BATN * FCN];         // relu(layer2)[:, :512]
__device__ float g_y1p[KCH1 * BATN * LSN]; // K-split partials layer 1
__device__ float g_y2p[KCH2 * BATN * FCN]; // K-split partials layer 2
__device__ float g_T[NCHMAX][DMAX];        // per-chunk diagonal totals
__device__ float g_O[NCHMAX][DMAX];        // per-chunk diagonal prefix offsets

// ---------------- cumulative products (d = [1, cumprod(subd)]) ----------------
__global__ void scan_kernel(const float* __restrict__ sa1, const float* __restrict__ sb1,
                            const float* __restrict__ sa2, const float* __restrict__ sb2) {
    const float* s;
    int w = blockIdx.x;
    if (w == 0) s = sa1; else if (w == 1) s = sb1; else if (w == 2) s = sa2; else s = sb2;
    float* d  = g_d[2 * w];
    float* di = g_d[2 * w + 1];
    __shared__ float sh[1024];
    int t = threadIdx.x;
    int base = 4 * t;
    float v0 = (base + 0 < LSN - 1) ? s[base + 0] : 1.f;
    float v1 = (base + 1 < LSN - 1) ? s[base + 1] : 1.f;
    float v2 = (base + 2 < LSN - 1) ? s[base + 2] : 1.f;
    float v3 = (base + 3 < LSN - 1) ? s[base + 3] : 1.f;
    sh[t] = v0 * v1 * v2 * v3;
    __syncthreads();
    for (int off = 1; off < 1024; off <<= 1) {
        float val = sh[t];
        if (t >= off) val *= sh[t - off];
        __syncthreads();
        sh[t] = val;
        __syncthreads();
    }
    float E = (t == 0) ? 1.f : sh[t - 1];
    float p0 = E, p1 = p0 * v0, p2 = p1 * v1, p3 = p2 * v2;
    d[base + 0] = p0; d[base + 1] = p1; d[base + 2] = p2; d[base + 3] = p3;
    di[base + 0] = 1.f / p0; di[base + 1] = 1.f / p1;
    di[base + 2] = 1.f / p2; di[base + 3] = 1.f / p3;
}

// ---------------- z1 = x * db1 ----------------
__global__ void z1prep_kernel(const float* __restrict__ x) {
    int idx = blockIdx.x * blockDim.x + threadIdx.x;   // 64*1024
    int k = idx & (NIN - 1);
    g_z1[idx] = x[idx] * g_d[2][k];
}

// ---------------- rank-K outer-product GEMM with diagonal rescale epilogue ----------------
// out[r, c] = (1/dR[r]) * (1/dC[c]) * sum_i P[i, r] * Q[i, c]   (P,Q rows have stride LSN)
template<int RR, int KD, int IR, int IC, int OB>
__global__ void gemmA_kernel(const float* __restrict__ P, const float* __restrict__ Q) {
    float* out = OB ? g_buf2 : g_buf1;
    __shared__ float shP[16][64];
    __shared__ float shQ[16][64];
    int r0 = blockIdx.y * 64, c0 = blockIdx.x * 64;
    int tid = threadIdx.x;
    int tx = tid & 15, ty = tid >> 4;
    float acc[4][4] = {};
    for (int i0 = 0; i0 < KD; i0 += 16) {
        #pragma unroll
        for (int it = 0; it < 4; ++it) {
            int e = it * 256 + tid;
            int kk = e >> 6, rc = e & 63;
            shP[kk][rc] = P[(i0 + kk) * LSN + r0 + rc];
            shQ[kk][rc] = Q[(i0 + kk) * LSN + c0 + rc];
        }
        __syncthreads();
        #pragma unroll
        for (int kk = 0; kk < 16; ++kk) {
            float a[4], b[4];
            #pragma unroll
            for (int u = 0; u < 4; ++u) a[u] = shP[kk][ty * 4 + u];
            #pragma unroll
            for (int v = 0; v < 4; ++v) b[v] = shQ[kk][tx * 4 + v];
            #pragma unroll
            for (int u = 0; u < 4; ++u)
                #pragma unroll
                for (int v = 0; v < 4; ++v) acc[u][v] += a[u] * b[v];
        }
        __syncthreads();
    }
    #pragma unroll
    for (int u = 0; u < 4; ++u) {
        int r = r0 + ty * 4 + u;
        float ir = g_d[IR][r];
        #pragma unroll
        for (int v = 0; v < 4; ++v) {
            int c = c0 + tx * 4 + v;
            out[r * LSN + c] = ir * g_d[IC][c] * acc[u][v];
        }
    }
}

// ---------------- chunked diagonal cumulative sum: C[r,c] = C[r-1,c-1] + A[r,c] ----------------
// Phase 1: in-place local cumsum within DCH-row chunks; per-chunk totals -> g_T.
template<int R, int OB>
__global__ void diag_local_kernel() {
    float* buf = OB ? g_buf2 : g_buf1;
    constexpr int NSTART = LSN + DCH - 1;
    int j = blockIdx.x * blockDim.x + threadIdx.x;
    if (j >= NSTART) return;
    int q = blockIdx.y;
    int r0, c0;
    if (j < LSN) { r0 = q * DCH; c0 = j; }
    else         { r0 = q * DCH + (j - LSN + 1); c0 = 0; }
    int lenA = DCH - (r0 - q * DCH);
    int lenB = LSN - c0;
    int len = lenA < lenB ? lenA : lenB;
    int idx = r0 * LSN + c0;
    float acc = 0.f;
    #pragma unroll 4
    for (int s = 0; s < len; ++s) {
        acc += buf[idx];
        buf[idx] = acc;
        idx += LSN + 1;
    }
    int d = c0 - r0 + (R - 1);
    g_T[q][d] = acc;
}

// Phase 2: exclusive prefix of chunk totals along each global diagonal -> g_O.
template<int R, int NCH>
__global__ void diag_offsets_kernel() {
    int d = blockIdx.x * blockDim.x + threadIdx.x;
    if (d >= R + LSN - 1) return;
    int dd = d - (R - 1);
    float acc = 0.f;
    #pragma unroll
    for (int q = 0; q < NCH; ++q) {
        g_O[q][d] = acc;
        int rt = q * DCH, rb = rt + DCH - 1;
        if ((rt + dd < LSN) && (rb + dd >= 0)) acc += g_T[q][d];
    }
}

// Phase 3: add diagonal prefix offsets to chunks >= 1 (float4 on buf, scalar O).
template<int R, int OB>
__global__ void diag_fix_kernel() {
    float* buf = OB ? g_buf2 : g_buf1;
    int e = blockIdx.x * blockDim.x + threadIdx.x;
    int idx = e * 4 + DCH * LSN;                  // skip chunk 0
    if (idx >= R * LSN) return;
    int r = idx >> 12;                            // / LSN
    int c = idx & (LSN - 1);
    int q = r / DCH;
    int d = c - r + (R - 1);
    const float* Oq = g_O[q];
    float4 v = *reinterpret_cast<float4*>(buf + idx);
    v.x += Oq[d];
    v.y += Oq[d + 1];
    v.z += Oq[d + 2];
    v.w += Oq[d + 3];
    *reinterpret_cast<float4*>(buf + idx) = v;
}

// ---------------- apply GEMM: OUT(64 x N) = A(64 x KT) @ B, K-split into partials ----------------
template<int LAYER>
__global__ void gemm64_kernel() {
    constexpr int N  = (LAYER == 1) ? LSN : FCN;
    constexpr int KT = (LAYER == 1) ? NIN : LSN;
    constexpr int KC = (LAYER == 1) ? KC1 : KC2;
    constexpr int BT = (LAYER == 1) ? 0 : 1;     // BT=1: B stored as (N rows x KT cols)
    const float* A = (LAYER == 1) ? g_z1 : g_z2;
    const float* B = (LAYER == 1) ? g_buf1 : g_buf2;
    float* O = (LAYER == 1) ? g_y1p : g_y2p;
    __shared__ float shA[64][33];
    __shared__ float shB[32][65];
    int j0 = blockIdx.x * 64;
    int k0 = blockIdx.y * KC;
    int tid = threadIdx.x;
    int tx = tid & 15, ty = tid >> 4;
    float acc[4][4] = {};
    for (int ks = 0; ks < KC; ks += 32) {
        int kb = k0 + ks;
        #pragma unroll
        for (int it = 0; it < 8; ++it) {
            int e = it * 256 + tid;
            int bb = e >> 5, kk = e & 31;
            shA[bb][kk] = A[bb * KT + kb + kk];
        }
        if (BT == 0) {
            #pragma unroll
            for (int it = 0; it < 8; ++it) {
                int e = it * 256 + tid;
                int kk = e >> 6, jj = e & 63;
                shB[kk][jj] = B[(kb + kk) * N + j0 + jj];
            }
        } else {
            #pragma unroll
            for (int it = 0; it < 8; ++it) {
                int e = it * 256 + tid;
                int jj = e >> 5, kk = e & 31;
                shB[kk][jj] = B[(j0 + jj) * KT + kb + kk];
            }
        }
        __syncthreads();
        #pragma unroll
        for (int kk = 0; kk < 32; ++kk) {
            float a[4], b[4];
            #pragma unroll
            for (int u = 0; u < 4; ++u) a[u] = shA[ty * 4 + u][kk];
            #pragma unroll
            for (int v = 0; v < 4; ++v) b[v] = shB[kk][tx * 4 + v];
            #pragma unroll
            for (int u = 0; u < 4; ++u)
                #pragma unroll
                for (int v = 0; v < 4; ++v) acc[u][v] += a[u] * b[v];
        }
        __syncthreads();
    }
    #pragma unroll
    for (int u = 0; u < 4; ++u) {
        int bb = ty * 4 + u;
        #pragma unroll
        for (int v = 0; v < 4; ++v) {
            int j = j0 + tx * 4 + v;
            O[blockIdx.y * (64 * N) + bb * N + j] = acc[u][v];
        }
    }
}

// ---------------- reduce K-split partials + layer epilogues ----------------
__global__ void reduce1_kernel(const float* __restrict__ bias1) {
    int idx = blockIdx.x * blockDim.x + threadIdx.x;   // 64*4096
    int b = idx >> 12, j = idx & (LSN - 1);
    float s = 0.f;
    #pragma unroll
    for (int c = 0; c < KCH1; ++c) s += g_y1p[c * (BATN * LSN) + b * LSN + j];
    float h = g_d[0][j] * s + bias1[j];
    h = h > 0.f ? h : 0.f;
    g_z2[b * LSN + j] = h * g_d[6][j];
}

__global__ void reduce2_kernel(const float* __restrict__ bias2) {
    int idx = blockIdx.x * blockDim.x + threadIdx.x;   // 64*512
    int b = idx >> 9, j = idx & (FCN - 1);
    float s = 0.f;
    #pragma unroll
    for (int c = 0; c < KCH2; ++c) s += g_y2p[c * (BATN * FCN) + b * FCN + j];
    float h = g_d[4][j] * s + bias2[j];
    g_h2[b * FCN + j] = h > 0.f ? h : 0.f;
}

// ---------------- logits: warp per (b, c) ----------------
__global__ void logits_kernel(const float* __restrict__ W, const float* __restrict__ bl,
                              float* __restrict__ out) {
    int warp = (blockIdx.x * blockDim.x + threadIdx.x) >> 5;
    int lane = threadIdx.x & 31;
    if (warp >= BATN * NCLS) return;
    int b = warp / NCLS, c = warp % NCLS;
    const float* hrow = g_h2 + b * FCN;
    const float* wrow = W + c * FCN;
    float s = 0.f;
    for (int j = lane; j < FCN; j += 32) s += hrow[j] * wrow[j];
    #pragma unroll
    for (int off = 16; off; off >>= 1) s += __shfl_xor_sync(0xffffffffu, s, off);
    if (lane == 0) out[b * NCLS + c] = s + bl[c];
}

// ---------------- launch ----------------
extern "C" void kernel_launch(void* const* d_in, const int* in_sizes, int n_in,
                              void* d_out, int out_size) {
    (void)in_sizes; (void)n_in; (void)out_size;
    const float* x      = (const float*)d_in[0];
    const float* G1     = (const float*)d_in[1];
    const float* H1     = (const float*)d_in[2];
    const float* sA1    = (const float*)d_in[3];
    const float* sB1    = (const float*)d_in[4];
    const float* bias1  = (const float*)d_in[5];
    const float* G2     = (const float*)d_in[6];
    const float* H2     = (const float*)d_in[7];
    const float* sA2    = (const float*)d_in[8];
    const float* sB2    = (const float*)d_in[9];
    const float* bias2  = (const float*)d_in[10];
    const float* W      = (const float*)d_in[11];
    const float* bl     = (const float*)d_in[12];
    float* out = (float*)d_out;

    constexpr int NSTART = LSN + DCH - 1;           // 4159
    constexpr int NCH1 = NIN / DCH;                 // 16
    constexpr int NCH2 = FCN / DCH;                 // 8
    constexpr int D1 = NIN + LSN - 1;               // 5119
    constexpr int D2 = FCN + LSN - 1;               // 4607

    // cumprods + reciprocals
    scan_kernel<<<4, 1024>>>(sA1, sB1, sA2, sB2);
    // z1 = x * db1
    z1prep_kernel<<<(BATN * NIN) / 256, 256>>>(x);
    // A1^T (1024 x 4096): rows k scaled 1/db1, cols j scaled 1/da1, rank 48
    gemmA_kernel<NIN, 48, 3, 1, 0><<<dim3(LSN / 64, NIN / 64), 256>>>(H1, G1);
    // C1^T in place: chunked diagonal cumsum
    diag_local_kernel<NIN, 0><<<dim3((NSTART + 255) / 256, NCH1), 256>>>();
    diag_offsets_kernel<NIN, NCH1><<<(D1 + 255) / 256, 256>>>();
    diag_fix_kernel<NIN, 0><<<((NIN - DCH) * LSN / 4 + 255) / 256, 256>>>();
    // Y1 partials: z1(64x1024) @ C1^T(1024x4096), K split into 8
    gemm64_kernel<1><<<dim3(LSN / 64, KCH1), 256>>>();
    // z2 = relu(da1*Y1 + bias1) * db2
    reduce1_kernel<<<(BATN * LSN) / 256, 256>>>(bias1);
    // A2 (512 x 4096): rows j scaled 1/da2, cols k scaled 1/db2, rank 16
    gemmA_kernel<FCN, 16, 5, 7, 1><<<dim3(LSN / 64, FCN / 64), 256>>>(G2, H2);
    // C2 in place: chunked diagonal cumsum
    diag_local_kernel<FCN, 1><<<dim3((NSTART + 255) / 256, NCH2), 256>>>();
    diag_offsets_kernel<FCN, NCH2><<<(D2 + 255) / 256, 256>>>();
    diag_fix_kernel<FCN, 1><<<((FCN - DCH) * LSN / 4 + 255) / 256, 256>>>();
    // Y2 partials: z2(64x4096) @ C2^T(4096x512), K split into 16
    gemm64_kernel<2><<<dim3(FCN / 64, KCH2), 256>>>();
    // h2 = relu(da2*Y2 + bias2)
    reduce2_kernel<<<(BATN * FCN) / 256, 256>>>(bias2);
    // logits
    logits_kernel<<<(BATN * NCLS * 32 + 255) / 256, 256>>>(W, bl, out);
}

// round 3
// speedup vs baseline: 4.4526x; 1.1288x over previous
#include <cuda_runtime.h>

#define LSN 4096   // layer size
#define NIN 1024   // input length (x columns)
#define BATN 64    // batch
#define FCN 512    // fc slice
#define NCLS 10

#define KCH1 4
#define KC1 256    // KCH1*KC1 = 1024
#define KCH2 16
#define KC2 256    // KCH2*KC2 = 4096

#define DCH 32           // diag-scan chunk height
#define DMAX 5120        // >= LSN + NIN - 1
#define NCH1 (NIN / DCH) // 32
#define NCH2 (FCN / DCH) // 16

// ---------------- static scratch (no allocations allowed) ----------------
// g_d rows: 0=da1 1=1/da1 2=db1 3=1/db1 4=da2 5=1/da2 6=db2 7=1/db2
__device__ float g_d[8][LSN];
__device__ float g_buf1[NIN * LSN];        // A1^T then locally-scanned C1^T : 1024 x 4096 (rows=k, cols=j)
__device__ float g_buf2[FCN * LSN];        // A2 then locally-scanned C2     : 512  x 4096 (rows=j, cols=k)
__device__ float g_z1[BATN * NIN];         // x * db1
__device__ float g_z2[BATN * LSN];         // relu(layer1) scaled by db2
__device__ float g_h2[BATN * FCN];         // relu(layer2)[:, :512]
__device__ float g_y1p[KCH1 * BATN * LSN]; // K-split partials layer 1
__device__ float g_y2p[KCH2 * BATN * FCN]; // K-split partials layer 2
__device__ float g_T1[NCH1][DMAX];         // per-chunk diagonal totals (layer 1)
__device__ float g_O1[NCH1][DMAX];         // per-chunk diagonal prefix offsets (layer 1)
__device__ float g_T2[NCH2][DMAX];
__device__ float g_O2[NCH2][DMAX];

// ---------------- cumulative products (d = [1, cumprod(subd)]) + z1 = x*db1 ----------------
__global__ void scan_kernel(const float* __restrict__ sa1, const float* __restrict__ sb1,
                            const float* __restrict__ sa2, const float* __restrict__ sb2,
                            const float* __restrict__ x) {
    const float* s;
    int w = blockIdx.x;
    if (w == 0) s = sa1; else if (w == 1) s = sb1; else if (w == 2) s = sa2; else s = sb2;
    float* d  = g_d[2 * w];
    float* di = g_d[2 * w + 1];
    __shared__ float sh[1024];
    int t = threadIdx.x;
    int base = 4 * t;
    float v0 = (base + 0 < LSN - 1) ? s[base + 0] : 1.f;
    float v1 = (base + 1 < LSN - 1) ? s[base + 1] : 1.f;
    float v2 = (base + 2 < LSN - 1) ? s[base + 2] : 1.f;
    float v3 = (base + 3 < LSN - 1) ? s[base + 3] : 1.f;
    sh[t] = v0 * v1 * v2 * v3;
    __syncthreads();
    for (int off = 1; off < 1024; off <<= 1) {
        float val = sh[t];
        if (t >= off) val *= sh[t - off];
        __syncthreads();
        sh[t] = val;
        __syncthreads();
    }
    float E = (t == 0) ? 1.f : sh[t - 1];
    float p0 = E, p1 = p0 * v0, p2 = p1 * v1, p3 = p2 * v2;
    d[base + 0] = p0; d[base + 1] = p1; d[base + 2] = p2; d[base + 3] = p3;
    di[base + 0] = 1.f / p0; di[base + 1] = 1.f / p1;
    di[base + 2] = 1.f / p2; di[base + 3] = 1.f / p3;
    if (w == 1) {
        // block 1 owns db1; fuse z1 = x * db1
        __syncthreads();
        for (int idx = t; idx < BATN * NIN; idx += 1024)
            g_z1[idx] = x[idx] * d[idx & (NIN - 1)];
    }
}

// ---------------- rank-K outer-product GEMM with diagonal rescale epilogue ----------------
// out[r, c] = (1/dR[r]) * (1/dC[c]) * sum_i P[i, r] * Q[i, c]   (P,Q rows have stride LSN)
template<int RR, int KD, int IR, int IC, int OB>
__global__ void gemmA_kernel(const float* __restrict__ P, const float* __restrict__ Q) {
    float* out = OB ? g_buf2 : g_buf1;
    __shared__ float shP[16][64];
    __shared__ float shQ[16][64];
    int r0 = blockIdx.y * 64, c0 = blockIdx.x * 64;
    int tid = threadIdx.x;
    int tx = tid & 15, ty = tid >> 4;
    float acc[4][4] = {};
    for (int i0 = 0; i0 < KD; i0 += 16) {
        {
            int kk = tid >> 4, rc4 = (tid & 15) * 4;
            *reinterpret_cast<float4*>(&shP[kk][rc4]) =
                *reinterpret_cast<const float4*>(P + (i0 + kk) * LSN + r0 + rc4);
            *reinterpret_cast<float4*>(&shQ[kk][rc4]) =
                *reinterpret_cast<const float4*>(Q + (i0 + kk) * LSN + c0 + rc4);
        }
        __syncthreads();
        #pragma unroll
        for (int kk = 0; kk < 16; ++kk) {
            float a[4], b[4];
            #pragma unroll
            for (int u = 0; u < 4; ++u) a[u] = shP[kk][ty * 4 + u];
            #pragma unroll
            for (int v = 0; v < 4; ++v) b[v] = shQ[kk][tx * 4 + v];
            #pragma unroll
            for (int u = 0; u < 4; ++u)
                #pragma unroll
                for (int v = 0; v < 4; ++v) acc[u][v] += a[u] * b[v];
        }
        __syncthreads();
    }
    #pragma unroll
    for (int u = 0; u < 4; ++u) {
        int r = r0 + ty * 4 + u;
        float ir = g_d[IR][r];
        int c = c0 + tx * 4;
        float4 o;
        o.x = ir * g_d[IC][c + 0] * acc[u][0];
        o.y = ir * g_d[IC][c + 1] * acc[u][1];
        o.z = ir * g_d[IC][c + 2] * acc[u][2];
        o.w = ir * g_d[IC][c + 3] * acc[u][3];
        *reinterpret_cast<float4*>(out + r * LSN + c) = o;
    }
}

// ---------------- chunked diagonal cumulative sum (local pass) ----------------
// In-place local cumsum within DCH-row chunks; per-chunk totals -> T.
template<int R, int OB>
__global__ void diag_local_kernel() {
    float* buf = OB ? g_buf2 : g_buf1;
    float (*T)[DMAX] = OB ? g_T2 : g_T1;
    constexpr int NSTART = LSN + DCH - 1;
    int j = blockIdx.x * blockDim.x + threadIdx.x;
    if (j >= NSTART) return;
    int q = blockIdx.y;
    int r0, c0;
    if (j < LSN) { r0 = q * DCH; c0 = j; }
    else         { r0 = q * DCH + (j - LSN + 1); c0 = 0; }
    int lenA = DCH - (r0 - q * DCH);
    int lenB = LSN - c0;
    int len = lenA < lenB ? lenA : lenB;
    int idx = r0 * LSN + c0;
    float acc = 0.f;
    #pragma unroll 8
    for (int s = 0; s < len; ++s) {
        acc += buf[idx];
        buf[idx] = acc;
        idx += LSN + 1;
    }
    T[q][c0 - r0 + (R - 1)] = acc;
}

// Exclusive prefix of chunk totals along each global diagonal -> O.
template<int R, int NCH, int OB>
__global__ void diag_offsets_kernel() {
    float (*T)[DMAX] = OB ? g_T2 : g_T1;
    float (*O)[DMAX] = OB ? g_O2 : g_O1;
    int d = blockIdx.x * blockDim.x + threadIdx.x;
    if (d >= R + LSN - 1) return;
    int dd = d - (R - 1);
    float acc = 0.f;
    #pragma unroll
    for (int q = 0; q < NCH; ++q) {
        O[q][d] = acc;
        int rt = q * DCH, rb = rt + DCH - 1;
        if ((rt + dd < LSN) && (rb + dd >= 0)) acc += T[q][d];
    }
}

// ---------------- apply GEMM: OUT(64 x N) = A(64 x KT) @ C, K-split into partials ----------------
// C is reconstructed on the fly: C[r,c] = buf[r,c] + O[r/DCH][c - r + R-1]
template<int LAYER>
__global__ void gemm64_kernel() {
    constexpr int N  = (LAYER == 1) ? LSN : FCN;
    constexpr int KT = (LAYER == 1) ? NIN : LSN;
    constexpr int KC = (LAYER == 1) ? KC1 : KC2;
    constexpr int R  = (LAYER == 1) ? NIN : FCN;
    constexpr int BT = (LAYER == 1) ? 0 : 1;     // BT=1: B stored as (N rows x KT cols)
    const float* A = (LAYER == 1) ? g_z1 : g_z2;
    const float* B = (LAYER == 1) ? g_buf1 : g_buf2;
    float (*O)[DMAX] = (LAYER == 1) ? g_O1 : g_O2;
    float* OUT = (LAYER == 1) ? g_y1p : g_y2p;
    __shared__ float shA[64][36];
    __shared__ float shB[32][68];
    int j0 = blockIdx.x * 64;
    int k0 = blockIdx.y * KC;
    int tid = threadIdx.x;
    int tx = tid & 15, ty = tid >> 4;
    float acc[4][4] = {};
    for (int ks = 0; ks < KC; ks += 32) {
        int kb = k0 + ks;
        // load A tile 64 x 32 (float4)
        #pragma unroll
        for (int it = 0; it < 2; ++it) {
            int e = it * 256 + tid;
            int bb = e >> 3, kk4 = (e & 7) * 4;
            *reinterpret_cast<float4*>(&shA[bb][kk4]) =
                *reinterpret_cast<const float4*>(A + bb * KT + kb + kk4);
        }
        // load B tile with fused diagonal-offset add
        if (BT == 0) {
            // buf rows = k, cols = j
            #pragma unroll
            for (int it = 0; it < 2; ++it) {
                int e = it * 256 + tid;
                int kk = e >> 4, jj4 = (e & 15) * 4;
                int kg = kb + kk;
                float4 v = *reinterpret_cast<const float4*>(B + kg * LSN + j0 + jj4);
                const float* Oq = O[kg >> 5];   // DCH = 32
                int d = (j0 + jj4) - kg + (R - 1);
                v.x += Oq[d]; v.y += Oq[d + 1]; v.z += Oq[d + 2]; v.w += Oq[d + 3];
                *reinterpret_cast<float4*>(&shB[kk][jj4]) = v;
            }
        } else {
            // buf rows = j, cols = k
            #pragma unroll
            for (int it = 0; it < 2; ++it) {
                int e = it * 256 + tid;
                int jj = e >> 3, kk4 = (e & 7) * 4;
                int jg = j0 + jj;
                float4 v = *reinterpret_cast<const float4*>(B + jg * KT + kb + kk4);
                const float* Oq = O[jg >> 5];
                int d = (kb + kk4) - jg + (R - 1);
                shB[kk4 + 0][jj] = v.x + Oq[d];
                shB[kk4 + 1][jj] = v.y + Oq[d + 1];
                shB[kk4 + 2][jj] = v.z + Oq[d + 2];
                shB[kk4 + 3][jj] = v.w + Oq[d + 3];
            }
        }
        __syncthreads();
        #pragma unroll
        for (int kk = 0; kk < 32; ++kk) {
            float a[4], b[4];
            #pragma unroll
            for (int u = 0; u < 4; ++u) a[u] = shA[ty * 4 + u][kk];
            #pragma unroll
            for (int v = 0; v < 4; ++v) b[v] = shB[kk][tx * 4 + v];
            #pragma unroll
            for (int u = 0; u < 4; ++u)
                #pragma unroll
                for (int v = 0; v < 4; ++v) acc[u][v] += a[u] * b[v];
        }
        __syncthreads();
    }
    #pragma unroll
    for (int u = 0; u < 4; ++u) {
        int bb = ty * 4 + u;
        float4 o = make_float4(acc[u][0], acc[u][1], acc[u][2], acc[u][3]);
        *reinterpret_cast<float4*>(OUT + blockIdx.y * (64 * N) + bb * N + j0 + tx * 4) = o;
    }
}

// ---------------- reduce K-split partials + layer epilogues ----------------
__global__ void reduce1_kernel(const float* __restrict__ bias1) {
    int idx = blockIdx.x * blockDim.x + threadIdx.x;   // 64*4096
    int b = idx >> 12, j = idx & (LSN - 1);
    float s = 0.f;
    #pragma unroll
    for (int c = 0; c < KCH1; ++c) s += g_y1p[c * (BATN * LSN) + b * LSN + j];
    float h = g_d[0][j] * s + bias1[j];
    h = h > 0.f ? h : 0.f;
    g_z2[b * LSN + j] = h * g_d[6][j];
}

__global__ void reduce2_kernel(const float* __restrict__ bias2) {
    int idx = blockIdx.x * blockDim.x + threadIdx.x;   // 64*512
    int b = idx >> 9, j = idx & (FCN - 1);
    float s = 0.f;
    #pragma unroll
    for (int c = 0; c < KCH2; ++c) s += g_y2p[c * (BATN * FCN) + b * FCN + j];
    float h = g_d[4][j] * s + bias2[j];
    g_h2[b * FCN + j] = h > 0.f ? h : 0.f;
}

// ---------------- logits: warp per (b, c) ----------------
__global__ void logits_kernel(const float* __restrict__ W, const float* __restrict__ bl,
                              float* __restrict__ out) {
    int warp = (blockIdx.x * blockDim.x + threadIdx.x) >> 5;
    int lane = threadIdx.x & 31;
    if (warp >= BATN * NCLS) return;
    int b = warp / NCLS, c = warp % NCLS;
    const float* hrow = g_h2 + b * FCN;
    const float* wrow = W + c * FCN;
    float s = 0.f;
    for (int j = lane; j < FCN; j += 32) s += hrow[j] * wrow[j];
    #pragma unroll
    for (int off = 16; off; off >>= 1) s += __shfl_xor_sync(0xffffffffu, s, off);
    if (lane == 0) out[b * NCLS + c] = s + bl[c];
}

// ---------------- launch ----------------
extern "C" void kernel_launch(void* const* d_in, const int* in_sizes, int n_in,
                              void* d_out, int out_size) {
    (void)in_sizes; (void)n_in; (void)out_size;
    const float* x      = (const float*)d_in[0];
    const float* G1     = (const float*)d_in[1];
    const float* H1     = (const float*)d_in[2];
    const float* sA1    = (const float*)d_in[3];
    const float* sB1    = (const float*)d_in[4];
    const float* bias1  = (const float*)d_in[5];
    const float* G2     = (const float*)d_in[6];
    const float* H2     = (const float*)d_in[7];
    const float* sA2    = (const float*)d_in[8];
    const float* sB2    = (const float*)d_in[9];
    const float* bias2  = (const float*)d_in[10];
    const float* W      = (const float*)d_in[11];
    const float* bl     = (const float*)d_in[12];
    float* out = (float*)d_out;

    constexpr int NSTART = LSN + DCH - 1;           // 4127
    constexpr int D1 = NIN + LSN - 1;               // 5119
    constexpr int D2 = FCN + LSN - 1;               // 4607

    // cumprods + reciprocals + z1 = x*db1
    scan_kernel<<<4, 1024>>>(sA1, sB1, sA2, sB2, x);
    // A1^T (1024 x 4096): rows k scaled 1/db1, cols j scaled 1/da1, rank 48
    gemmA_kernel<NIN, 48, 3, 1, 0><<<dim3(LSN / 64, NIN / 64), 256>>>(H1, G1);
    // C1^T: chunk-local diagonal cumsum + offsets (fix-up fused into gemm64)
    diag_local_kernel<NIN, 0><<<dim3((NSTART + 255) / 256, NCH1), 256>>>();
    diag_offsets_kernel<NIN, NCH1, 0><<<(D1 + 255) / 256, 256>>>();
    // Y1 partials: z1(64x1024) @ C1^T(1024x4096), K split into 4
    gemm64_kernel<1><<<dim3(LSN / 64, KCH1), 256>>>();
    // z2 = relu(da1*Y1 + bias1) * db2
    reduce1_kernel<<<(BATN * LSN) / 256, 256>>>(bias1);
    // A2 (512 x 4096): rows j scaled 1/da2, cols k scaled 1/db2, rank 16
    gemmA_kernel<FCN, 16, 5, 7, 1><<<dim3(LSN / 64, FCN / 64), 256>>>(G2, H2);
    // C2: chunk-local diagonal cumsum + offsets
    diag_local_kernel<FCN, 1><<<dim3((NSTART + 255) / 256, NCH2), 256>>>();
    diag_offsets_kernel<FCN, NCH2, 1><<<(D2 + 255) / 256, 256>>>();
    // Y2 partials: z2(64x4096) @ C2^T(4096x512), K split into 16
    gemm64_kernel<2><<<dim3(FCN / 64, KCH2), 256>>>();
    // h2 = relu(da2*Y2 + bias2)
    reduce2_kernel<<<(BATN * FCN) / 256, 256>>>(bias2);
    // logits
    logits_kernel<<<(BATN * NCLS * 32 + 255) / 256, 256>>>(W, bl, out);
}

// round 4
// speedup vs baseline: 4.9379x; 1.1090x over previous
#include <cuda_runtime.h>

#define LSN 4096   // layer size
#define NIN 1024   // input length (x columns)
#define BATN 64    // batch
#define FCN 512    // fc slice
#define NCLS 10

#define KCH1 4
#define KC1 256    // KCH1*KC1 = 1024
#define KCH2 16
#define KC2 256    // KCH2*KC2 = 4096

#define DCH 32           // diag-scan chunk height
#define DMAX 5120        // >= LSN + NIN - 1
#define NCH1 (NIN / DCH) // 32
#define NCH2 (FCN / DCH) // 16

// ---------------- static scratch (no allocations allowed) ----------------
// g_d rows: 0=da1 1=1/da1 2=db1 3=1/db1 4=da2 5=1/da2 6=db2 7=1/db2
__device__ float g_d[8][LSN];
__device__ float g_buf1[NIN * LSN];        // A1^T then locally-scanned C1^T : 1024 x 4096 (rows=k, cols=j)
__device__ float g_buf2[FCN * LSN];        // A2 then locally-scanned C2     : 512  x 4096 (rows=j, cols=k)
__device__ float g_z1[BATN * NIN];         // x * db1
__device__ float g_z2[BATN * LSN];         // relu(layer1) scaled by db2
__device__ float g_h2[BATN * FCN];         // relu(layer2)[:, :512]
__device__ float g_y1p[KCH1 * BATN * LSN]; // K-split partials layer 1
__device__ float g_y2p[KCH2 * BATN * FCN]; // K-split partials layer 2
__device__ float g_T1t[DMAX * NCH1];       // per-chunk diagonal totals, TRANSPOSED [d][q]
__device__ float g_T2t[DMAX * NCH2];
__device__ float g_O1[NCH1][DMAX];         // per-chunk diagonal prefix offsets [q][d]
__device__ float g_O2[NCH2][DMAX];

// ---------------- cumulative products (d = [1, cumprod(subd)]) + z1 = x*db1 ----------------
__global__ void scan_kernel(const float* __restrict__ sa1, const float* __restrict__ sb1,
                            const float* __restrict__ sa2, const float* __restrict__ sb2,
                            const float* __restrict__ x) {
    const float* s;
    int w = blockIdx.x;
    if (w == 0) s = sa1; else if (w == 1) s = sb1; else if (w == 2) s = sa2; else s = sb2;
    float* d  = g_d[2 * w];
    float* di = g_d[2 * w + 1];
    __shared__ float sh[1024];
    int t = threadIdx.x;
    int base = 4 * t;
    float v0 = (base + 0 < LSN - 1) ? s[base + 0] : 1.f;
    float v1 = (base + 1 < LSN - 1) ? s[base + 1] : 1.f;
    float v2 = (base + 2 < LSN - 1) ? s[base + 2] : 1.f;
    float v3 = (base + 3 < LSN - 1) ? s[base + 3] : 1.f;
    sh[t] = v0 * v1 * v2 * v3;
    __syncthreads();
    for (int off = 1; off < 1024; off <<= 1) {
        float val = sh[t];
        if (t >= off) val *= sh[t - off];
        __syncthreads();
        sh[t] = val;
        __syncthreads();
    }
    float E = (t == 0) ? 1.f : sh[t - 1];
    float p0 = E, p1 = p0 * v0, p2 = p1 * v1, p3 = p2 * v2;
    d[base + 0] = p0; d[base + 1] = p1; d[base + 2] = p2; d[base + 3] = p3;
    di[base + 0] = 1.f / p0; di[base + 1] = 1.f / p1;
    di[base + 2] = 1.f / p2; di[base + 3] = 1.f / p3;
    if (w == 1) {
        // block 1 owns db1; fuse z1 = x * db1
        __syncthreads();
        for (int idx = t; idx < BATN * NIN; idx += 1024)
            g_z1[idx] = x[idx] * d[idx & (NIN - 1)];
    }
}

// ---------------- rank-K outer-product GEMM with diagonal rescale epilogue ----------------
// out[r, c] = (1/dR[r]) * (1/dC[c]) * sum_i P[i, r] * Q[i, c]   (P,Q rows have stride LSN)
template<int RR, int KD, int IR, int IC, int OB>
__global__ void gemmA_kernel(const float* __restrict__ P, const float* __restrict__ Q) {
    float* out = OB ? g_buf2 : g_buf1;
    __shared__ float shP[16][64];
    __shared__ float shQ[16][64];
    int r0 = blockIdx.y * 64, c0 = blockIdx.x * 64;
    int tid = threadIdx.x;
    int tx = tid & 15, ty = tid >> 4;
    float acc[4][4] = {};
    for (int i0 = 0; i0 < KD; i0 += 16) {
        {
            int kk = tid >> 4, rc4 = (tid & 15) * 4;
            *reinterpret_cast<float4*>(&shP[kk][rc4]) =
                *reinterpret_cast<const float4*>(P + (i0 + kk) * LSN + r0 + rc4);
            *reinterpret_cast<float4*>(&shQ[kk][rc4]) =
                *reinterpret_cast<const float4*>(Q + (i0 + kk) * LSN + c0 + rc4);
        }
        __syncthreads();
        #pragma unroll
        for (int kk = 0; kk < 16; ++kk) {
            float a[4], b[4];
            #pragma unroll
            for (int u = 0; u < 4; ++u) a[u] = shP[kk][ty * 4 + u];
            #pragma unroll
            for (int v = 0; v < 4; ++v) b[v] = shQ[kk][tx * 4 + v];
            #pragma unroll
            for (int u = 0; u < 4; ++u)
                #pragma unroll
                for (int v = 0; v < 4; ++v) acc[u][v] += a[u] * b[v];
        }
        __syncthreads();
    }
    #pragma unroll
    for (int u = 0; u < 4; ++u) {
        int r = r0 + ty * 4 + u;
        float ir = g_d[IR][r];
        int c = c0 + tx * 4;
        float4 o;
        o.x = ir * g_d[IC][c + 0] * acc[u][0];
        o.y = ir * g_d[IC][c + 1] * acc[u][1];
        o.z = ir * g_d[IC][c + 2] * acc[u][2];
        o.w = ir * g_d[IC][c + 3] * acc[u][3];
        *reinterpret_cast<float4*>(out + r * LSN + c) = o;
    }
}

// ---------------- chunked diagonal cumulative sum (local pass) ----------------
// In-place local cumsum within DCH-row chunks; per-chunk totals -> Tt[d][q].
template<int R, int NCH, int OB>
__global__ void diag_local_kernel() {
    float* buf = OB ? g_buf2 : g_buf1;
    float* Tt = OB ? g_T2t : g_T1t;
    constexpr int NSTART = LSN + DCH - 1;
    int j = blockIdx.x * blockDim.x + threadIdx.x;
    if (j >= NSTART) return;
    int q = blockIdx.y;
    int r0, c0;
    if (j < LSN) { r0 = q * DCH; c0 = j; }
    else         { r0 = q * DCH + (j - LSN + 1); c0 = 0; }
    int lenA = DCH - (r0 - q * DCH);
    int lenB = LSN - c0;
    int len = lenA < lenB ? lenA : lenB;
    int idx = r0 * LSN + c0;
    float acc = 0.f;
    #pragma unroll 8
    for (int s = 0; s < len; ++s) {
        acc += buf[idx];
        buf[idx] = acc;
        idx += LSN + 1;
    }
    int d = c0 - r0 + (R - 1);
    Tt[d * NCH + q] = acc;
}

// Exclusive prefix of chunk totals along each global diagonal -> O[q][d].
// Thread d reads its whole Tt row (contiguous, float4) into registers, scans there.
template<int R, int NCH, int OB>
__global__ void diag_offsets_kernel() {
    const float* Tt = OB ? g_T2t : g_T1t;
    float (*O)[DMAX] = OB ? g_O2 : g_O1;
    int d = blockIdx.x * blockDim.x + threadIdx.x;
    if (d >= R + LSN - 1) return;
    int dd = d - (R - 1);
    float t[NCH];
    const float4* p = reinterpret_cast<const float4*>(Tt + d * NCH);
    #pragma unroll
    for (int i = 0; i < NCH / 4; ++i) {
        float4 v = p[i];
        t[4 * i + 0] = v.x; t[4 * i + 1] = v.y;
        t[4 * i + 2] = v.z; t[4 * i + 3] = v.w;
    }
    float acc = 0.f;
    #pragma unroll
    for (int q = 0; q < NCH; ++q) {
        O[q][d] = acc;
        int rt = q * DCH, rb = rt + DCH - 1;
        if ((rt + dd < LSN) && (rb + dd >= 0)) acc += t[q];
    }
}

// ---------------- apply GEMM: OUT(64 x N) = A(64 x KT) @ C, K-split into partials ----------------
// C is reconstructed on the fly: C[r,c] = buf[r,c] + O[r/DCH][c - r + R-1]
template<int LAYER>
__global__ void gemm64_kernel() {
    constexpr int N  = (LAYER == 1) ? LSN : FCN;
    constexpr int KT = (LAYER == 1) ? NIN : LSN;
    constexpr int KC = (LAYER == 1) ? KC1 : KC2;
    constexpr int R  = (LAYER == 1) ? NIN : FCN;
    constexpr int BT = (LAYER == 1) ? 0 : 1;     // BT=1: B stored as (N rows x KT cols)
    const float* A = (LAYER == 1) ? g_z1 : g_z2;
    const float* B = (LAYER == 1) ? g_buf1 : g_buf2;
    float (*O)[DMAX] = (LAYER == 1) ? g_O1 : g_O2;
    float* OUT = (LAYER == 1) ? g_y1p : g_y2p;
    __shared__ float shA[64][36];
    __shared__ float shB[32][68];
    int j0 = blockIdx.x * 64;
    int k0 = blockIdx.y * KC;
    int tid = threadIdx.x;
    int tx = tid & 15, ty = tid >> 4;
    float acc[4][4] = {};
    for (int ks = 0; ks < KC; ks += 32) {
        int kb = k0 + ks;
        // load A tile 64 x 32 (float4)
        #pragma unroll
        for (int it = 0; it < 2; ++it) {
            int e = it * 256 + tid;
            int bb = e >> 3, kk4 = (e & 7) * 4;
            *reinterpret_cast<float4*>(&shA[bb][kk4]) =
                *reinterpret_cast<const float4*>(A + bb * KT + kb + kk4);
        }
        // load B tile with fused diagonal-offset add
        if (BT == 0) {
            // buf rows = k, cols = j
            #pragma unroll
            for (int it = 0; it < 2; ++it) {
                int e = it * 256 + tid;
                int kk = e >> 4, jj4 = (e & 15) * 4;
                int kg = kb + kk;
                float4 v = *reinterpret_cast<const float4*>(B + kg * LSN + j0 + jj4);
                const float* Oq = O[kg >> 5];   // DCH = 32
                int d = (j0 + jj4) - kg + (R - 1);
                v.x += Oq[d]; v.y += Oq[d + 1]; v.z += Oq[d + 2]; v.w += Oq[d + 3];
                *reinterpret_cast<float4*>(&shB[kk][jj4]) = v;
            }
        } else {
            // buf rows = j, cols = k
            #pragma unroll
            for (int it = 0; it < 2; ++it) {
                int e = it * 256 + tid;
                int jj = e >> 3, kk4 = (e & 7) * 4;
                int jg = j0 + jj;
                float4 v = *reinterpret_cast<const float4*>(B + jg * KT + kb + kk4);
                const float* Oq = O[jg >> 5];
                int d = (kb + kk4) - jg + (R - 1);
                shB[kk4 + 0][jj] = v.x + Oq[d];
                shB[kk4 + 1][jj] = v.y + Oq[d + 1];
                shB[kk4 + 2][jj] = v.z + Oq[d + 2];
                shB[kk4 + 3][jj] = v.w + Oq[d + 3];
            }
        }
        __syncthreads();
        #pragma unroll
        for (int kk = 0; kk < 32; ++kk) {
            float a[4], b[4];
            #pragma unroll
            for (int u = 0; u < 4; ++u) a[u] = shA[ty * 4 + u][kk];
            #pragma unroll
            for (int v = 0; v < 4; ++v) b[v] = shB[kk][tx * 4 + v];
            #pragma unroll
            for (int u = 0; u < 4; ++u)
                #pragma unroll
                for (int v = 0; v < 4; ++v) acc[u][v] += a[u] * b[v];
        }
        __syncthreads();
    }
    #pragma unroll
    for (int u = 0; u < 4; ++u) {
        int bb = ty * 4 + u;
        float4 o = make_float4(acc[u][0], acc[u][1], acc[u][2], acc[u][3]);
        *reinterpret_cast<float4*>(OUT + blockIdx.y * (64 * N) + bb * N + j0 + tx * 4) = o;
    }
}

// ---------------- reduce K-split partials + layer epilogues ----------------
__global__ void reduce1_kernel(const float* __restrict__ bias1) {
    int idx = blockIdx.x * blockDim.x + threadIdx.x;   // 64*4096
    int b = idx >> 12, j = idx & (LSN - 1);
    float s = 0.f;
    #pragma unroll
    for (int c = 0; c < KCH1; ++c) s += g_y1p[c * (BATN * LSN) + b * LSN + j];
    float h = g_d[0][j] * s + bias1[j];
    h = h > 0.f ? h : 0.f;
    g_z2[b * LSN + j] = h * g_d[6][j];
}

__global__ void reduce2_kernel(const float* __restrict__ bias2) {
    int idx = blockIdx.x * blockDim.x + threadIdx.x;   // 64*512
    int b = idx >> 9, j = idx & (FCN - 1);
    float s = 0.f;
    #pragma unroll
    for (int c = 0; c < KCH2; ++c) s += g_y2p[c * (BATN * FCN) + b * FCN + j];
    float h = g_d[4][j] * s + bias2[j];
    g_h2[b * FCN + j] = h > 0.f ? h : 0.f;
}

// ---------------- logits: warp per (b, c) ----------------
__global__ void logits_kernel(const float* __restrict__ W, const float* __restrict__ bl,
                              float* __restrict__ out) {
    int warp = (blockIdx.x * blockDim.x + threadIdx.x) >> 5;
    int lane = threadIdx.x & 31;
    if (warp >= BATN * NCLS) return;
    int b = warp / NCLS, c = warp % NCLS;
    const float* hrow = g_h2 + b * FCN;
    const float* wrow = W + c * FCN;
    float s = 0.f;
    for (int j = lane; j < FCN; j += 32) s += hrow[j] * wrow[j];
    #pragma unroll
    for (int off = 16; off; off >>= 1) s += __shfl_xor_sync(0xffffffffu, s, off);
    if (lane == 0) out[b * NCLS + c] = s + bl[c];
}

// ---------------- launch ----------------
extern "C" void kernel_launch(void* const* d_in, const int* in_sizes, int n_in,
                              void* d_out, int out_size) {
    (void)in_sizes; (void)n_in; (void)out_size;
    const float* x      = (const float*)d_in[0];
    const float* G1     = (const float*)d_in[1];
    const float* H1     = (const float*)d_in[2];
    const float* sA1    = (const float*)d_in[3];
    const float* sB1    = (const float*)d_in[4];
    const float* bias1  = (const float*)d_in[5];
    const float* G2     = (const float*)d_in[6];
    const float* H2     = (const float*)d_in[7];
    const float* sA2    = (const float*)d_in[8];
    const float* sB2    = (const float*)d_in[9];
    const float* bias2  = (const float*)d_in[10];
    const float* W      = (const float*)d_in[11];
    const float* bl     = (const float*)d_in[12];
    float* out = (float*)d_out;

    constexpr int NSTART = LSN + DCH - 1;           // 4127
    constexpr int D1 = NIN + LSN - 1;               // 5119
    constexpr int D2 = FCN + LSN - 1;               // 4607

    // cumprods + reciprocals + z1 = x*db1
    scan_kernel<<<4, 1024>>>(sA1, sB1, sA2, sB2, x);
    // A1^T (1024 x 4096): rows k scaled 1/db1, cols j scaled 1/da1, rank 48
    gemmA_kernel<NIN, 48, 3, 1, 0><<<dim3(LSN / 64, NIN / 64), 256>>>(H1, G1);
    // C1^T: chunk-local diagonal cumsum + register-scan offsets (fix-up fused into gemm64)
    diag_local_kernel<NIN, NCH1, 0><<<dim3((NSTART + 255) / 256, NCH1), 256>>>();
    diag_offsets_kernel<NIN, NCH1, 0><<<(D1 + 255) / 256, 256>>>();
    // Y1 partials: z1(64x1024) @ C1^T(1024x4096), K split into 4
    gemm64_kernel<1><<<dim3(LSN / 64, KCH1), 256>>>();
    // z2 = relu(da1*Y1 + bias1) * db2
    reduce1_kernel<<<(BATN * LSN) / 256, 256>>>(bias1);
    // A2 (512 x 4096): rows j scaled 1/da2, cols k scaled 1/db2, rank 16
    gemmA_kernel<FCN, 16, 5, 7, 1><<<dim3(LSN / 64, FCN / 64), 256>>>(G2, H2);
    // C2: chunk-local diagonal cumsum + register-scan offsets
    diag_local_kernel<FCN, NCH2, 1><<<dim3((NSTART + 255) / 256, NCH2), 256>>>();
    diag_offsets_kernel<FCN, NCH2, 1><<<(D2 + 255) / 256, 256>>>();
    // Y2 partials: z2(64x4096) @ C2^T(4096x512), K split into 16
    gemm64_kernel<2><<<dim3(FCN / 64, KCH2), 256>>>();
    // h2 = relu(da2*Y2 + bias2)
    reduce2_kernel<<<(BATN * FCN) / 256, 256>>>(bias2);
    // logits
    logits_kernel<<<(BATN * NCLS * 32 + 255) / 256, 256>>>(W, bl, out);
}

// round 5
// speedup vs baseline: 5.5846x; 1.1310x over previous
#include <cuda_runtime.h>

#define LSN 4096   // layer size
#define NIN 1024   // input length (x columns)
#define BATN 64    // batch
#define FCN 512    // fc slice
#define NCLS 10

#define KCH1 4
#define KC1 256    // KCH1*KC1 = 1024
#define KCH2 16
#define KC2 256    // KCH2*KC2 = 4096

#define DCH 32           // diag-scan chunk height
#define DMAX 5120        // >= LSN + NIN - 1
#define NCH1 (NIN / DCH) // 32
#define NCH2 (FCN / DCH) // 16

// ---------------- static scratch (no allocations allowed) ----------------
// g_d rows: 0=da1 1=1/da1 2=db1 3=1/db1 4=da2 5=1/da2 6=db2 7=1/db2
__device__ float g_d[8][LSN];
__device__ float g_buf1[NIN * LSN];        // A1^T then locally-scanned C1^T : rows=k, cols=j
__device__ float g_buf2[FCN * LSN];        // A2 then locally-scanned C2     : rows=j, cols=k
__device__ float g_z1[BATN * NIN];         // x * db1
__device__ float g_z2[BATN * LSN];         // relu(layer1) scaled by db2
__device__ float g_y1p[KCH1 * BATN * LSN]; // K-split partials layer 1
__device__ float g_y2p[KCH2 * BATN * FCN]; // K-split partials layer 2
__device__ float g_T1t[DMAX * NCH1];       // per-chunk diagonal totals, transposed [d][q]
__device__ float g_T2t[DMAX * NCH2];
__device__ float g_O1[NCH1][DMAX];         // per-chunk diagonal prefix offsets [q][d]
__device__ float g_O2[NCH2][DMAX];

// ---------------- cumulative products (d = [1, cumprod(subd)]) + z1 = x*db1 ----------------
__global__ void scan_kernel(const float* __restrict__ sa1, const float* __restrict__ sb1,
                            const float* __restrict__ sa2, const float* __restrict__ sb2,
                            const float* __restrict__ x) {
    const float* s;
    int w = blockIdx.x;
    if (w == 0) s = sa1; else if (w == 1) s = sb1; else if (w == 2) s = sa2; else s = sb2;
    float* d  = g_d[2 * w];
    float* di = g_d[2 * w + 1];
    __shared__ float sh[1024];
    int t = threadIdx.x;
    int base = 4 * t;
    float v0 = (base + 0 < LSN - 1) ? s[base + 0] : 1.f;
    float v1 = (base + 1 < LSN - 1) ? s[base + 1] : 1.f;
    float v2 = (base + 2 < LSN - 1) ? s[base + 2] : 1.f;
    float v3 = (base + 3 < LSN - 1) ? s[base + 3] : 1.f;
    sh[t] = v0 * v1 * v2 * v3;
    __syncthreads();
    for (int off = 1; off < 1024; off <<= 1) {
        float val = sh[t];
        if (t >= off) val *= sh[t - off];
        __syncthreads();
        sh[t] = val;
        __syncthreads();
    }
    float E = (t == 0) ? 1.f : sh[t - 1];
    float p0 = E, p1 = p0 * v0, p2 = p1 * v1, p3 = p2 * v2;
    d[base + 0] = p0; d[base + 1] = p1; d[base + 2] = p2; d[base + 3] = p3;
    di[base + 0] = 1.f / p0; di[base + 1] = 1.f / p1;
    di[base + 2] = 1.f / p2; di[base + 3] = 1.f / p3;
    if (w == 1) {
        __syncthreads();
        for (int idx = t; idx < BATN * NIN; idx += 1024)
            g_z1[idx] = x[idx] * d[idx & (NIN - 1)];
    }
}

// ---------------- gemmA body: out[r,c] = (1/dR[r])(1/dC[c]) sum_i P[i,r] Q[i,c] ----------------
template<int KD, int IR, int IC>
__device__ __forceinline__ void gemmA_body(const float* __restrict__ P, const float* __restrict__ Q,
                                           float* __restrict__ out,
                                           float (*shP)[64], float (*shQ)[64],
                                           int r0, int c0) {
    int tid = threadIdx.x;
    int tx = tid & 15, ty = tid >> 4;
    float acc[4][4] = {};
    for (int i0 = 0; i0 < KD; i0 += 16) {
        {
            int kk = tid >> 4, rc4 = (tid & 15) * 4;
            *reinterpret_cast<float4*>(&shP[kk][rc4]) =
                *reinterpret_cast<const float4*>(P + (i0 + kk) * LSN + r0 + rc4);
            *reinterpret_cast<float4*>(&shQ[kk][rc4]) =
                *reinterpret_cast<const float4*>(Q + (i0 + kk) * LSN + c0 + rc4);
        }
        __syncthreads();
        #pragma unroll
        for (int kk = 0; kk < 16; ++kk) {
            float a[4], b[4];
            #pragma unroll
            for (int u = 0; u < 4; ++u) a[u] = shP[kk][ty * 4 + u];
            #pragma unroll
            for (int v = 0; v < 4; ++v) b[v] = shQ[kk][tx * 4 + v];
            #pragma unroll
            for (int u = 0; u < 4; ++u)
                #pragma unroll
                for (int v = 0; v < 4; ++v) acc[u][v] += a[u] * b[v];
        }
        __syncthreads();
    }
    #pragma unroll
    for (int u = 0; u < 4; ++u) {
        int r = r0 + ty * 4 + u;
        float ir = g_d[IR][r];
        int c = c0 + tx * 4;
        float4 o;
        o.x = ir * g_d[IC][c + 0] * acc[u][0];
        o.y = ir * g_d[IC][c + 1] * acc[u][1];
        o.z = ir * g_d[IC][c + 2] * acc[u][2];
        o.w = ir * g_d[IC][c + 3] * acc[u][3];
        *reinterpret_cast<float4*>(out + r * LSN + c) = o;
    }
}

// fused: gemmA1 (1024 blocks) + gemmA2 (512 blocks)
__global__ void fused_gemmA_kernel(const float* __restrict__ G1, const float* __restrict__ H1,
                                   const float* __restrict__ G2, const float* __restrict__ H2) {
    __shared__ float shP[16][64];
    __shared__ float shQ[16][64];
    int b = blockIdx.x;
    if (b < 1024) {
        gemmA_body<48, 3, 1>(H1, G1, g_buf1, shP, shQ, (b >> 6) * 64, (b & 63) * 64);
    } else {
        b -= 1024;
        gemmA_body<16, 5, 7>(G2, H2, g_buf2, shP, shQ, (b >> 6) * 64, (b & 63) * 64);
    }
}

// ---------------- chunk-local diagonal cumsum; totals -> Tt[d][q] ----------------
template<int R, int NCH, int OB>
__device__ __forceinline__ void diag_local_body(int xblk, int q) {
    float* buf = OB ? g_buf2 : g_buf1;
    float* Tt = OB ? g_T2t : g_T1t;
    constexpr int NSTART = LSN + DCH - 1;
    int j = xblk * 256 + threadIdx.x;
    if (j >= NSTART) return;
    int r0, c0;
    if (j < LSN) { r0 = q * DCH; c0 = j; }
    else         { r0 = q * DCH + (j - LSN + 1); c0 = 0; }
    int lenA = DCH - (r0 - q * DCH);
    int lenB = LSN - c0;
    int len = lenA < lenB ? lenA : lenB;
    int idx = r0 * LSN + c0;
    float acc = 0.f;
    #pragma unroll 8
    for (int s = 0; s < len; ++s) {
        acc += buf[idx];
        buf[idx] = acc;
        idx += LSN + 1;
    }
    Tt[(c0 - r0 + (R - 1)) * NCH + q] = acc;
}

__global__ void diag_local1_kernel() {
    diag_local_body<NIN, NCH1, 0>(blockIdx.x, blockIdx.y);
}

// ---------------- register prefix-scan of chunk totals -> O[q][d] ----------------
template<int R, int NCH, int OB>
__device__ __forceinline__ void diag_offsets_body(int xblk) {
    const float* Tt = OB ? g_T2t : g_T1t;
    float (*O)[DMAX] = OB ? g_O2 : g_O1;
    int d = xblk * 256 + threadIdx.x;
    if (d >= R + LSN - 1) return;
    int dd = d - (R - 1);
    float t[NCH];
    const float4* p = reinterpret_cast<const float4*>(Tt + d * NCH);
    #pragma unroll
    for (int i = 0; i < NCH / 4; ++i) {
        float4 v = p[i];
        t[4 * i + 0] = v.x; t[4 * i + 1] = v.y;
        t[4 * i + 2] = v.z; t[4 * i + 3] = v.w;
    }
    float acc = 0.f;
    #pragma unroll
    for (int q = 0; q < NCH; ++q) {
        O[q][d] = acc;
        int rt = q * DCH, rb = rt + DCH - 1;
        if ((rt + dd < LSN) && (rb + dd >= 0)) acc += t[q];
    }
}

// fused: diag_offsets1 (20 blocks) + diag_local2 (17*16 = 272 blocks)
__global__ void fused_off1_loc2_kernel() {
    int b = blockIdx.x;
    if (b < 20) {
        diag_offsets_body<NIN, NCH1, 0>(b);
    } else {
        b -= 20;
        diag_local_body<FCN, NCH2, 1>(b % 17, b / 17);
    }
}

// ---------------- apply GEMM body: OUT(64 x N) = A(64 x KT) @ C, K-split ----------------
// C reconstructed on the fly: C[r,c] = buf[r,c] + O[r/DCH][c - r + R-1]
template<int LAYER>
__device__ __forceinline__ void gemm64_body(int jblk, int kblk,
                                            float (*shA)[36], float (*shB)[68]) {
    constexpr int N  = (LAYER == 1) ? LSN : FCN;
    constexpr int KT = (LAYER == 1) ? NIN : LSN;
    constexpr int KC = (LAYER == 1) ? KC1 : KC2;
    constexpr int R  = (LAYER == 1) ? NIN : FCN;
    constexpr int BT = (LAYER == 1) ? 0 : 1;
    const float* A = (LAYER == 1) ? g_z1 : g_z2;
    const float* B = (LAYER == 1) ? g_buf1 : g_buf2;
    float (*O)[DMAX] = (LAYER == 1) ? g_O1 : g_O2;
    float* OUT = (LAYER == 1) ? g_y1p : g_y2p;
    int j0 = jblk * 64;
    int k0 = kblk * KC;
    int tid = threadIdx.x;
    int tx = tid & 15, ty = tid >> 4;
    float acc[4][4] = {};
    for (int ks = 0; ks < KC; ks += 32) {
        int kb = k0 + ks;
        #pragma unroll
        for (int it = 0; it < 2; ++it) {
            int e = it * 256 + tid;
            int bb = e >> 3, kk4 = (e & 7) * 4;
            *reinterpret_cast<float4*>(&shA[bb][kk4]) =
                *reinterpret_cast<const float4*>(A + bb * KT + kb + kk4);
        }
        if (BT == 0) {
            #pragma unroll
            for (int it = 0; it < 2; ++it) {
                int e = it * 256 + tid;
                int kk = e >> 4, jj4 = (e & 15) * 4;
                int kg = kb + kk;
                float4 v = *reinterpret_cast<const float4*>(B + kg * LSN + j0 + jj4);
                const float* Oq = O[kg >> 5];
                int d = (j0 + jj4) - kg + (R - 1);
                v.x += Oq[d]; v.y += Oq[d + 1]; v.z += Oq[d + 2]; v.w += Oq[d + 3];
                *reinterpret_cast<float4*>(&shB[kk][jj4]) = v;
            }
        } else {
            #pragma unroll
            for (int it = 0; it < 2; ++it) {
                int e = it * 256 + tid;
                int jj = e >> 3, kk4 = (e & 7) * 4;
                int jg = j0 + jj;
                float4 v = *reinterpret_cast<const float4*>(B + jg * KT + kb + kk4);
                const float* Oq = O[jg >> 5];
                int d = (kb + kk4) - jg + (R - 1);
                shB[kk4 + 0][jj] = v.x + Oq[d];
                shB[kk4 + 1][jj] = v.y + Oq[d + 1];
                shB[kk4 + 2][jj] = v.z + Oq[d + 2];
                shB[kk4 + 3][jj] = v.w + Oq[d + 3];
            }
        }
        __syncthreads();
        #pragma unroll
        for (int kk = 0; kk < 32; ++kk) {
            float a[4], b[4];
            #pragma unroll
            for (int u = 0; u < 4; ++u) a[u] = shA[ty * 4 + u][kk];
            #pragma unroll
            for (int v = 0; v < 4; ++v) b[v] = shB[kk][tx * 4 + v];
            #pragma unroll
            for (int u = 0; u < 4; ++u)
                #pragma unroll
                for (int v = 0; v < 4; ++v) acc[u][v] += a[u] * b[v];
        }
        __syncthreads();
    }
    #pragma unroll
    for (int u = 0; u < 4; ++u) {
        int bb = ty * 4 + u;
        float4 o = make_float4(acc[u][0], acc[u][1], acc[u][2], acc[u][3]);
        *reinterpret_cast<float4*>(OUT + kblk * (64 * N) + bb * N + j0 + tx * 4) = o;
    }
}

// fused: gemm64_1 (256 blocks) + diag_offsets2 (18 blocks)
__global__ void fused_g641_off2_kernel() {
    __shared__ float shA[64][36];
    __shared__ float shB[32][68];
    int b = blockIdx.x;
    if (b < 256) {
        gemm64_body<1>(b & 63, b >> 6, shA, shB);
    } else {
        diag_offsets_body<FCN, NCH2, 1>(b - 256);
    }
}

__global__ void gemm64_2_kernel() {
    __shared__ float shA[64][36];
    __shared__ float shB[32][68];
    gemm64_body<2>(blockIdx.x, blockIdx.y, shA, shB);
}

// ---------------- reduce1 (float4): z2 = relu(da1*sum(partials)+bias1)*db2 ----------------
__global__ void reduce1_kernel(const float* __restrict__ bias1) {
    int e = blockIdx.x * blockDim.x + threadIdx.x;     // 64*4096/4
    int idx = e * 4;
    int b = idx >> 12, j = idx & (LSN - 1);
    float4 s = *reinterpret_cast<const float4*>(&g_y1p[b * LSN + j]);
    #pragma unroll
    for (int c = 1; c < KCH1; ++c) {
        float4 p = *reinterpret_cast<const float4*>(&g_y1p[c * (BATN * LSN) + b * LSN + j]);
        s.x += p.x; s.y += p.y; s.z += p.z; s.w += p.w;
    }
    float4 da = *reinterpret_cast<const float4*>(&g_d[0][j]);
    float4 db = *reinterpret_cast<const float4*>(&g_d[6][j]);
    float4 bi = *reinterpret_cast<const float4*>(&bias1[j]);
    float4 o;
    o.x = fmaxf(da.x * s.x + bi.x, 0.f) * db.x;
    o.y = fmaxf(da.y * s.y + bi.y, 0.f) * db.y;
    o.z = fmaxf(da.z * s.z + bi.z, 0.f) * db.z;
    o.w = fmaxf(da.w * s.w + bi.w, 0.f) * db.w;
    *reinterpret_cast<float4*>(&g_z2[b * LSN + j]) = o;
}

// ---------------- tail: reduce2 + logits fused (block per batch row) ----------------
__global__ void tail_kernel(const float* __restrict__ bias2, const float* __restrict__ W,
                            const float* __restrict__ bl, float* __restrict__ out) {
    __shared__ float h[FCN];
    int b = blockIdx.x;
    int t = threadIdx.x;
    for (int j = t; j < FCN; j += 256) {
        float s = 0.f;
        #pragma unroll
        for (int c = 0; c < KCH2; ++c) s += g_y2p[c * (BATN * FCN) + b * FCN + j];
        float v = g_d[4][j] * s + bias2[j];
        h[j] = v > 0.f ? v : 0.f;
    }
    __syncthreads();
    int warp = t >> 5, lane = t & 31;
    for (int c = warp; c < NCLS; c += 8) {
        const float* wrow = W + c * FCN;
        float s = 0.f;
        #pragma unroll 4
        for (int j = lane; j < FCN; j += 32) s += h[j] * wrow[j];
        #pragma unroll
        for (int off = 16; off; off >>= 1) s += __shfl_xor_sync(0xffffffffu, s, off);
        if (lane == 0) out[b * NCLS + c] = s + bl[c];
    }
}

// ---------------- launch ----------------
extern "C" void kernel_launch(void* const* d_in, const int* in_sizes, int n_in,
                              void* d_out, int out_size) {
    (void)in_sizes; (void)n_in; (void)out_size;
    const float* x      = (const float*)d_in[0];
    const float* G1     = (const float*)d_in[1];
    const float* H1     = (const float*)d_in[2];
    const float* sA1    = (const float*)d_in[3];
    const float* sB1    = (const float*)d_in[4];
    const float* bias1  = (const float*)d_in[5];
    const float* G2     = (const float*)d_in[6];
    const float* H2     = (const float*)d_in[7];
    const float* sA2    = (const float*)d_in[8];
    const float* sB2    = (const float*)d_in[9];
    const float* bias2  = (const float*)d_in[10];
    const float* W      = (const float*)d_in[11];
    const float* bl     = (const float*)d_in[12];
    float* out = (float*)d_out;

    // K1: cumprods + reciprocals + z1 = x*db1
    scan_kernel<<<4, 1024>>>(sA1, sB1, sA2, sB2, x);
    // K2: A1^T and A2 rank-r builds, fused
    fused_gemmA_kernel<<<1536, 256>>>(G1, H1, G2, H2);
    // K3: chunk-local diagonal cumsum of buf1
    diag_local1_kernel<<<dim3(17, NCH1), 256>>>();
    // K4: offsets for layer 1 + chunk-local cumsum of buf2, fused
    fused_off1_loc2_kernel<<<20 + 17 * NCH2, 256>>>();
    // K5: Y1 partials (K-split 4) + offsets for layer 2, fused
    fused_g641_off2_kernel<<<256 + 18, 256>>>();
    // K6: z2 = relu(da1*Y1 + bias1) * db2
    reduce1_kernel<<<(BATN * LSN / 4) / 256, 256>>>(bias1);
    // K7: Y2 partials (K-split 16)
    gemm64_2_kernel<<<dim3(FCN / 64, KCH2), 256>>>();
    // K8: h2 = relu(da2*Y2 + bias2); logits = h2 @ W^T + b
    tail_kernel<<<BATN, 256>>>(bias2, W, bl, out);
}

// round 6
// speedup vs baseline: 5.6052x; 1.0037x over previous
#include <cuda_runtime.h>

#define LSN 4096   // layer size
#define NIN 1024   // input length (x columns)
#define BATN 64    // batch
#define FCN 512    // fc slice
#define NCLS 10

#define KCH1 4
#define KC1 256    // KCH1*KC1 = 1024
#define KCH2 16
#define KC2 256    // KCH2*KC2 = 4096

#define DCH 16           // diag-scan chunk height
#define DMAX 5120        // >= LSN + NIN - 1
#define NCH1 (NIN / DCH) // 64
#define NCH2 (FCN / DCH) // 32

// ---------------- static scratch (no allocations allowed) ----------------
// g_d rows: 0=da1 1=1/da1 2=db1 3=1/db1 4=da2 5=1/da2 6=db2 7=1/db2
__device__ float g_d[8][LSN];
__device__ float g_buf1[NIN * LSN];        // A1^T then locally-scanned C1^T : rows=k, cols=j
__device__ float g_buf2[FCN * LSN];        // A2 then locally-scanned C2     : rows=j, cols=k
__device__ float g_z1[BATN * NIN];         // x * db1
__device__ float g_z2[BATN * LSN];         // relu(layer1) scaled by db2
__device__ float g_y1p[KCH1 * BATN * LSN]; // K-split partials layer 1
__device__ float g_y2p[KCH2 * BATN * FCN]; // K-split partials layer 2
__device__ float g_T1t[DMAX * NCH1];       // per-chunk diagonal totals, transposed [d][q]
__device__ float g_T2t[DMAX * NCH2];
__device__ float g_O1[NCH1][DMAX];         // per-chunk diagonal prefix offsets [q][d]
__device__ float g_O2[NCH2][DMAX];

// ---------------- cumulative products (d = [1, cumprod(subd)]) + z1 = x*db1 ----------------
__global__ void scan_kernel(const float* __restrict__ sa1, const float* __restrict__ sb1,
                            const float* __restrict__ sa2, const float* __restrict__ sb2,
                            const float* __restrict__ x) {
    const float* s;
    int w = blockIdx.x;
    if (w == 0) s = sa1; else if (w == 1) s = sb1; else if (w == 2) s = sa2; else s = sb2;
    float* d  = g_d[2 * w];
    float* di = g_d[2 * w + 1];
    __shared__ float sh[1024];
    int t = threadIdx.x;
    int base = 4 * t;
    float v0 = (base + 0 < LSN - 1) ? s[base + 0] : 1.f;
    float v1 = (base + 1 < LSN - 1) ? s[base + 1] : 1.f;
    float v2 = (base + 2 < LSN - 1) ? s[base + 2] : 1.f;
    float v3 = (base + 3 < LSN - 1) ? s[base + 3] : 1.f;
    sh[t] = v0 * v1 * v2 * v3;
    __syncthreads();
    for (int off = 1; off < 1024; off <<= 1) {
        float val = sh[t];
        if (t >= off) val *= sh[t - off];
        __syncthreads();
        sh[t] = val;
        __syncthreads();
    }
    float E = (t == 0) ? 1.f : sh[t - 1];
    float p0 = E, p1 = p0 * v0, p2 = p1 * v1, p3 = p2 * v2;
    d[base + 0] = p0; d[base + 1] = p1; d[base + 2] = p2; d[base + 3] = p3;
    di[base + 0] = 1.f / p0; di[base + 1] = 1.f / p1;
    di[base + 2] = 1.f / p2; di[base + 3] = 1.f / p3;
    if (w == 1) {
        __syncthreads();
        for (int idx = t; idx < BATN * NIN; idx += 1024)
            g_z1[idx] = x[idx] * d[idx & (NIN - 1)];
    }
}

// ---------------- gemmA body: out[r,c] = (1/dR[r])(1/dC[c]) sum_i P[i,r] Q[i,c] ----------------
template<int KD, int IR, int IC>
__device__ __forceinline__ void gemmA_body(const float* __restrict__ P, const float* __restrict__ Q,
                                           float* __restrict__ out,
                                           float (*shP)[64], float (*shQ)[64],
                                           int r0, int c0) {
    int tid = threadIdx.x;
    int tx = tid & 15, ty = tid >> 4;
    float acc[4][4] = {};
    for (int i0 = 0; i0 < KD; i0 += 16) {
        {
            int kk = tid >> 4, rc4 = (tid & 15) * 4;
            *reinterpret_cast<float4*>(&shP[kk][rc4]) =
                *reinterpret_cast<const float4*>(P + (i0 + kk) * LSN + r0 + rc4);
            *reinterpret_cast<float4*>(&shQ[kk][rc4]) =
                *reinterpret_cast<const float4*>(Q + (i0 + kk) * LSN + c0 + rc4);
        }
        __syncthreads();
        #pragma unroll
        for (int kk = 0; kk < 16; ++kk) {
            float a[4], b[4];
            #pragma unroll
            for (int u = 0; u < 4; ++u) a[u] = shP[kk][ty * 4 + u];
            #pragma unroll
            for (int v = 0; v < 4; ++v) b[v] = shQ[kk][tx * 4 + v];
            #pragma unroll
            for (int u = 0; u < 4; ++u)
                #pragma unroll
                for (int v = 0; v < 4; ++v) acc[u][v] += a[u] * b[v];
        }
        __syncthreads();
    }
    #pragma unroll
    for (int u = 0; u < 4; ++u) {
        int r = r0 + ty * 4 + u;
        float ir = g_d[IR][r];
        int c = c0 + tx * 4;
        float4 o;
        o.x = ir * g_d[IC][c + 0] * acc[u][0];
        o.y = ir * g_d[IC][c + 1] * acc[u][1];
        o.z = ir * g_d[IC][c + 2] * acc[u][2];
        o.w = ir * g_d[IC][c + 3] * acc[u][3];
        *reinterpret_cast<float4*>(out + r * LSN + c) = o;
    }
}

// fused: gemmA1 (1024 blocks) + gemmA2 (512 blocks)
__global__ void fused_gemmA_kernel(const float* __restrict__ G1, const float* __restrict__ H1,
                                   const float* __restrict__ G2, const float* __restrict__ H2) {
    __shared__ float shP[16][64];
    __shared__ float shQ[16][64];
    int b = blockIdx.x;
    if (b < 1024) {
        gemmA_body<48, 3, 1>(H1, G1, g_buf1, shP, shQ, (b >> 6) * 64, (b & 63) * 64);
    } else {
        b -= 1024;
        gemmA_body<16, 5, 7>(G2, H2, g_buf2, shP, shQ, (b >> 6) * 64, (b & 63) * 64);
    }
}

// ---------------- chunk-local diagonal cumsum; totals -> Tt[d][q] ----------------
template<int R, int NCH, int OB>
__device__ __forceinline__ void diag_local_body(int xblk, int q) {
    float* buf = OB ? g_buf2 : g_buf1;
    float* Tt = OB ? g_T2t : g_T1t;
    constexpr int NSTART = LSN + DCH - 1;
    int j = xblk * 256 + threadIdx.x;
    if (j >= NSTART) return;
    int r0, c0;
    if (j < LSN) { r0 = q * DCH; c0 = j; }
    else         { r0 = q * DCH + (j - LSN + 1); c0 = 0; }
    int lenA = DCH - (r0 - q * DCH);
    int lenB = LSN - c0;
    int len = lenA < lenB ? lenA : lenB;
    int idx = r0 * LSN + c0;
    float acc = 0.f;
    #pragma unroll 8
    for (int s = 0; s < len; ++s) {
        acc += buf[idx];
        buf[idx] = acc;
        idx += LSN + 1;
    }
    Tt[(c0 - r0 + (R - 1)) * NCH + q] = acc;
}

// fused: local1 (17*64 = 1088 blocks) + local2 (17*32 = 544 blocks)
__global__ void fused_local_kernel() {
    int b = blockIdx.x;
    if (b < 17 * NCH1) {
        diag_local_body<NIN, NCH1, 0>(b % 17, b / 17);
    } else {
        b -= 17 * NCH1;
        diag_local_body<FCN, NCH2, 1>(b % 17, b / 17);
    }
}

// ---------------- register prefix-scan of chunk totals -> O[q][d] ----------------
template<int R, int NCH, int OB>
__device__ __forceinline__ void diag_offsets_body(int xblk) {
    const float* Tt = OB ? g_T2t : g_T1t;
    float (*O)[DMAX] = OB ? g_O2 : g_O1;
    int d = xblk * 256 + threadIdx.x;
    if (d >= R + LSN - 1) return;
    int dd = d - (R - 1);
    float t[NCH];
    const float4* p = reinterpret_cast<const float4*>(Tt + d * NCH);
    #pragma unroll
    for (int i = 0; i < NCH / 4; ++i) {
        float4 v = p[i];
        t[4 * i + 0] = v.x; t[4 * i + 1] = v.y;
        t[4 * i + 2] = v.z; t[4 * i + 3] = v.w;
    }
    float acc = 0.f;
    #pragma unroll
    for (int q = 0; q < NCH; ++q) {
        O[q][d] = acc;
        int rt = q * DCH, rb = rt + DCH - 1;
        if ((rt + dd < LSN) && (rb + dd >= 0)) acc += t[q];
    }
}

// fused: offsets1 (20 blocks) + offsets2 (18 blocks)
__global__ void fused_offsets_kernel() {
    int b = blockIdx.x;
    if (b < 20) diag_offsets_body<NIN, NCH1, 0>(b);
    else        diag_offsets_body<FCN, NCH2, 1>(b - 20);
}

// ---------------- apply GEMM body: OUT(64 x N) = A(64 x KT) @ C, K-split ----------------
// C reconstructed on the fly: C[r,c] = buf[r,c] + O[r/DCH][c - r + R-1]
template<int LAYER>
__device__ __forceinline__ void gemm64_body(int jblk, int kblk,
                                            float (*shA)[36], float (*shB)[68]) {
    constexpr int N  = (LAYER == 1) ? LSN : FCN;
    constexpr int KT = (LAYER == 1) ? NIN : LSN;
    constexpr int KC = (LAYER == 1) ? KC1 : KC2;
    constexpr int R  = (LAYER == 1) ? NIN : FCN;
    constexpr int BT = (LAYER == 1) ? 0 : 1;
    const float* A = (LAYER == 1) ? g_z1 : g_z2;
    const float* B = (LAYER == 1) ? g_buf1 : g_buf2;
    float (*O)[DMAX] = (LAYER == 1) ? g_O1 : g_O2;
    float* OUT = (LAYER == 1) ? g_y1p : g_y2p;
    int j0 = jblk * 64;
    int k0 = kblk * KC;
    int tid = threadIdx.x;
    int tx = tid & 15, ty = tid >> 4;
    float acc[4][4] = {};
    for (int ks = 0; ks < KC; ks += 32) {
        int kb = k0 + ks;
        #pragma unroll
        for (int it = 0; it < 2; ++it) {
            int e = it * 256 + tid;
            int bb = e >> 3, kk4 = (e & 7) * 4;
            *reinterpret_cast<float4*>(&shA[bb][kk4]) =
                *reinterpret_cast<const float4*>(A + bb * KT + kb + kk4);
        }
        if (BT == 0) {
            #pragma unroll
            for (int it = 0; it < 2; ++it) {
                int e = it * 256 + tid;
                int kk = e >> 4, jj4 = (e & 15) * 4;
                int kg = kb + kk;
                float4 v = *reinterpret_cast<const float4*>(B + kg * LSN + j0 + jj4);
                const float* Oq = O[kg >> 4];   // DCH = 16
                int d = (j0 + jj4) - kg + (R - 1);
                v.x += Oq[d]; v.y += Oq[d + 1]; v.z += Oq[d + 2]; v.w += Oq[d + 3];
                *reinterpret_cast<float4*>(&shB[kk][jj4]) = v;
            }
        } else {
            #pragma unroll
            for (int it = 0; it < 2; ++it) {
                int e = it * 256 + tid;
                int jj = e >> 3, kk4 = (e & 7) * 4;
                int jg = j0 + jj;
                float4 v = *reinterpret_cast<const float4*>(B + jg * KT + kb + kk4);
                const float* Oq = O[jg >> 4];
                int d = (kb + kk4) - jg + (R - 1);
                shB[kk4 + 0][jj] = v.x + Oq[d];
                shB[kk4 + 1][jj] = v.y + Oq[d + 1];
                shB[kk4 + 2][jj] = v.z + Oq[d + 2];
                shB[kk4 + 3][jj] = v.w + Oq[d + 3];
            }
        }
        __syncthreads();
        #pragma unroll
        for (int kk = 0; kk < 32; ++kk) {
            float a[4], b[4];
            #pragma unroll
            for (int u = 0; u < 4; ++u) a[u] = shA[ty * 4 + u][kk];
            #pragma unroll
            for (int v = 0; v < 4; ++v) b[v] = shB[kk][tx * 4 + v];
            #pragma unroll
            for (int u = 0; u < 4; ++u)
                #pragma unroll
                for (int v = 0; v < 4; ++v) acc[u][v] += a[u] * b[v];
        }
        __syncthreads();
    }
    #pragma unroll
    for (int u = 0; u < 4; ++u) {
        int bb = ty * 4 + u;
        float4 o = make_float4(acc[u][0], acc[u][1], acc[u][2], acc[u][3]);
        *reinterpret_cast<float4*>(OUT + kblk * (64 * N) + bb * N + j0 + tx * 4) = o;
    }
}

__global__ void gemm64_1_kernel() {
    __shared__ float shA[64][36];
    __shared__ float shB[32][68];
    gemm64_body<1>(blockIdx.x & 63, blockIdx.x >> 6, shA, shB);
}

__global__ void gemm64_2_kernel() {
    __shared__ float shA[64][36];
    __shared__ float shB[32][68];
    gemm64_body<2>(blockIdx.x, blockIdx.y, shA, shB);
}

// ---------------- reduce1 (float4): z2 = relu(da1*sum(partials)+bias1)*db2 ----------------
__global__ void reduce1_kernel(const float* __restrict__ bias1) {
    int e = blockIdx.x * blockDim.x + threadIdx.x;     // 64*4096/4
    int idx = e * 4;
    int b = idx >> 12, j = idx & (LSN - 1);
    float4 s = *reinterpret_cast<const float4*>(&g_y1p[b * LSN + j]);
    #pragma unroll
    for (int c = 1; c < KCH1; ++c) {
        float4 p = *reinterpret_cast<const float4*>(&g_y1p[c * (BATN * LSN) + b * LSN + j]);
        s.x += p.x; s.y += p.y; s.z += p.z; s.w += p.w;
    }
    float4 da = *reinterpret_cast<const float4*>(&g_d[0][j]);
    float4 db = *reinterpret_cast<const float4*>(&g_d[6][j]);
    float4 bi = *reinterpret_cast<const float4*>(&bias1[j]);
    float4 o;
    o.x = fmaxf(da.x * s.x + bi.x, 0.f) * db.x;
    o.y = fmaxf(da.y * s.y + bi.y, 0.f) * db.y;
    o.z = fmaxf(da.z * s.z + bi.z, 0.f) * db.z;
    o.w = fmaxf(da.w * s.w + bi.w, 0.f) * db.w;
    *reinterpret_cast<float4*>(&g_z2[b * LSN + j]) = o;
}

// ---------------- tail: reduce2 + logits fused (block per batch row) ----------------
__global__ void tail_kernel(const float* __restrict__ bias2, const float* __restrict__ W,
                            const float* __restrict__ bl, float* __restrict__ out) {
    __shared__ float h[FCN];
    int b = blockIdx.x;
    int t = threadIdx.x;
    for (int j = t; j < FCN; j += 256) {
        float s = 0.f;
        #pragma unroll
        for (int c = 0; c < KCH2; ++c) s += g_y2p[c * (BATN * FCN) + b * FCN + j];
        float v = g_d[4][j] * s + bias2[j];
        h[j] = v > 0.f ? v : 0.f;
    }
    __syncthreads();
    int warp = t >> 5, lane = t & 31;
    for (int c = warp; c < NCLS; c += 8) {
        const float* wrow = W + c * FCN;
        float s = 0.f;
        #pragma unroll 4
        for (int j = lane; j < FCN; j += 32) s += h[j] * wrow[j];
        #pragma unroll
        for (int off = 16; off; off >>= 1) s += __shfl_xor_sync(0xffffffffu, s, off);
        if (lane == 0) out[b * NCLS + c] = s + bl[c];
    }
}

// ---------------- launch ----------------
extern "C" void kernel_launch(void* const* d_in, const int* in_sizes, int n_in,
                              void* d_out, int out_size) {
    (void)in_sizes; (void)n_in; (void)out_size;
    const float* x      = (const float*)d_in[0];
    const float* G1     = (const float*)d_in[1];
    const float* H1     = (const float*)d_in[2];
    const float* sA1    = (const float*)d_in[3];
    const float* sB1    = (const float*)d_in[4];
    const float* bias1  = (const float*)d_in[5];
    const float* G2     = (const float*)d_in[6];
    const float* H2     = (const float*)d_in[7];
    const float* sA2    = (const float*)d_in[8];
    const float* sB2    = (const float*)d_in[9];
    const float* bias2  = (const float*)d_in[10];
    const float* W      = (const float*)d_in[11];
    const float* bl     = (const float*)d_in[12];
    float* out = (float*)d_out;

    // K1: cumprods + reciprocals + z1 = x*db1
    scan_kernel<<<4, 1024>>>(sA1, sB1, sA2, sB2, x);
    // K2: A1^T and A2 rank-r builds, fused
    fused_gemmA_kernel<<<1536, 256>>>(G1, H1, G2, H2);
    // K3: chunk-local diagonal cumsums of buf1 AND buf2, fused (both ready after K2)
    fused_local_kernel<<<17 * NCH1 + 17 * NCH2, 256>>>();
    // K4: register prefix-scan offsets for both layers, fused
    fused_offsets_kernel<<<38, 256>>>();
    // K5: Y1 partials (K-split 4)
    gemm64_1_kernel<<<256, 256>>>();
    // K6: z2 = relu(da1*Y1 + bias1) * db2
    reduce1_kernel<<<(BATN * LSN / 4) / 256, 256>>>(bias1);
    // K7: Y2 partials (K-split 16)
    gemm64_2_kernel<<<dim3(FCN / 64, KCH2), 256>>>();
    // K8: h2 = relu(da2*Y2 + bias2); logits = h2 @ W^T + b
    tail_kernel<<<BATN, 256>>>(bias2, W, bl, out);
}

// round 7
// speedup vs baseline: 5.6448x; 1.0071x over previous
#include <cuda_runtime.h>

#define LSN 4096   // layer size
#define NIN 1024   // input length (x columns)
#define BATN 64    // batch
#define FCN 512    // fc slice
#define NCLS 10

#define KCH1 4
#define KC1 256    // KCH1*KC1 = 1024
#define KCH2 16
#define KC2 256    // KCH2*KC2 = 4096

#define DCH 16           // diag-scan chunk height
#define DMAX 5120        // >= LSN + NIN - 1
#define NCH1 (NIN / DCH) // 64
#define NCH2 (FCN / DCH) // 32

// ---------------- static scratch (no allocations allowed) ----------------
// g_d rows: 0=da1 1=1/da1 2=db1 3=1/db1 4=da2 5=1/da2 6=db2 7=1/db2
__device__ float g_d[8][LSN];
__device__ float g_buf1[NIN * LSN];        // A1^T then locally-scanned C1^T : rows=k, cols=j
__device__ float g_buf2[FCN * LSN];        // A2 then locally-scanned C2     : rows=j, cols=k
__device__ float g_z1[BATN * NIN];         // x * db1
__device__ float g_z2[BATN * LSN];         // relu(layer1) scaled by db2
__device__ float g_y1p[KCH1 * BATN * LSN]; // K-split partials layer 1
__device__ float g_y2p[KCH2 * BATN * FCN]; // K-split partials layer 2
__device__ float g_T1t[DMAX * NCH1];       // per-chunk diagonal totals, transposed [d][q]
__device__ float g_T2t[DMAX * NCH2];
__device__ float g_O1[NCH1][DMAX];         // per-chunk diagonal prefix offsets [q][d]
__device__ float g_O2[NCH2][DMAX];
__device__ unsigned int g_cnt1[64];        // per-jblk completion counters for gemm64_1

// ---------------- cumprods via warp-shuffle scan + z1 = x*db1 ----------------
__global__ void scan_kernel(const float* __restrict__ sa1, const float* __restrict__ sb1,
                            const float* __restrict__ sa2, const float* __restrict__ sb2,
                            const float* __restrict__ x) {
    const float* s;
    int w = blockIdx.x;
    if (w == 0) s = sa1; else if (w == 1) s = sb1; else if (w == 2) s = sa2; else s = sb2;
    float* d  = g_d[2 * w];
    float* di = g_d[2 * w + 1];
    __shared__ float wtot[32];
    int t = threadIdx.x;
    int lane = t & 31, warp = t >> 5;
    int base = 4 * t;
    float v0 = (base + 0 < LSN - 1) ? s[base + 0] : 1.f;
    float v1 = (base + 1 < LSN - 1) ? s[base + 1] : 1.f;
    float v2 = (base + 2 < LSN - 1) ? s[base + 2] : 1.f;
    float v3 = (base + 3 < LSN - 1) ? s[base + 3] : 1.f;
    float p = v0 * v1 * v2 * v3;
    // inclusive product scan within warp
    float sp = p;
    #pragma unroll
    for (int off = 1; off < 32; off <<= 1) {
        float n = __shfl_up_sync(0xffffffffu, sp, off);
        if (lane >= off) sp *= n;
    }
    if (lane == 31) wtot[warp] = sp;
    __syncthreads();
    if (warp == 0) {
        float wv = wtot[lane];
        #pragma unroll
        for (int off = 1; off < 32; off <<= 1) {
            float n = __shfl_up_sync(0xffffffffu, wv, off);
            if (lane >= off) wv *= n;
        }
        wtot[lane] = wv;
    }
    __syncthreads();
    float warpbase = (warp == 0) ? 1.f : wtot[warp - 1];
    float eprev = __shfl_up_sync(0xffffffffu, sp, 1);
    if (lane == 0) eprev = 1.f;
    float E = warpbase * eprev;                 // exclusive product up to this thread
    float p0 = E, p1 = p0 * v0, p2 = p1 * v1, p3 = p2 * v2;
    d[base + 0] = p0; d[base + 1] = p1; d[base + 2] = p2; d[base + 3] = p3;
    di[base + 0] = 1.f / p0; di[base + 1] = 1.f / p1;
    di[base + 2] = 1.f / p2; di[base + 3] = 1.f / p3;
    if (w == 1) {
        __syncthreads();
        for (int idx = t; idx < BATN * NIN; idx += 1024)
            g_z1[idx] = x[idx] * d[idx & (NIN - 1)];
    }
}

// ---------------- gemmA body: out[r,c] = (1/dR[r])(1/dC[c]) sum_i P[i,r] Q[i,c] ----------------
template<int KD, int IR, int IC>
__device__ __forceinline__ void gemmA_body(const float* __restrict__ P, const float* __restrict__ Q,
                                           float* __restrict__ out,
                                           float (*shP)[64], float (*shQ)[64],
                                           int r0, int c0) {
    int tid = threadIdx.x;
    int tx = tid & 15, ty = tid >> 4;
    float acc[4][4] = {};
    for (int i0 = 0; i0 < KD; i0 += 16) {
        {
            int kk = tid >> 4, rc4 = (tid & 15) * 4;
            *reinterpret_cast<float4*>(&shP[kk][rc4]) =
                *reinterpret_cast<const float4*>(P + (i0 + kk) * LSN + r0 + rc4);
            *reinterpret_cast<float4*>(&shQ[kk][rc4]) =
                *reinterpret_cast<const float4*>(Q + (i0 + kk) * LSN + c0 + rc4);
        }
        __syncthreads();
        #pragma unroll
        for (int kk = 0; kk < 16; ++kk) {
            float a[4], b[4];
            #pragma unroll
            for (int u = 0; u < 4; ++u) a[u] = shP[kk][ty * 4 + u];
            #pragma unroll
            for (int v = 0; v < 4; ++v) b[v] = shQ[kk][tx * 4 + v];
            #pragma unroll
            for (int u = 0; u < 4; ++u)
                #pragma unroll
                for (int v = 0; v < 4; ++v) acc[u][v] += a[u] * b[v];
        }
        __syncthreads();
    }
    #pragma unroll
    for (int u = 0; u < 4; ++u) {
        int r = r0 + ty * 4 + u;
        float ir = g_d[IR][r];
        int c = c0 + tx * 4;
        float4 o;
        o.x = ir * g_d[IC][c + 0] * acc[u][0];
        o.y = ir * g_d[IC][c + 1] * acc[u][1];
        o.z = ir * g_d[IC][c + 2] * acc[u][2];
        o.w = ir * g_d[IC][c + 3] * acc[u][3];
        *reinterpret_cast<float4*>(out + r * LSN + c) = o;
    }
}

// fused: gemmA1 (1024 blocks) + gemmA2 (512 blocks)
__global__ void fused_gemmA_kernel(const float* __restrict__ G1, const float* __restrict__ H1,
                                   const float* __restrict__ G2, const float* __restrict__ H2) {
    __shared__ float shP[16][64];
    __shared__ float shQ[16][64];
    int b = blockIdx.x;
    if (b < 1024) {
        gemmA_body<48, 3, 1>(H1, G1, g_buf1, shP, shQ, (b >> 6) * 64, (b & 63) * 64);
    } else {
        b -= 1024;
        gemmA_body<16, 5, 7>(G2, H2, g_buf2, shP, shQ, (b >> 6) * 64, (b & 63) * 64);
    }
}

// ---------------- chunk-local diagonal cumsum; totals -> Tt[d][q] ----------------
template<int R, int NCH, int OB>
__device__ __forceinline__ void diag_local_body(int xblk, int q) {
    float* buf = OB ? g_buf2 : g_buf1;
    float* Tt = OB ? g_T2t : g_T1t;
    constexpr int NSTART = LSN + DCH - 1;
    int j = xblk * 256 + threadIdx.x;
    if (j >= NSTART) return;
    int r0, c0;
    if (j < LSN) { r0 = q * DCH; c0 = j; }
    else         { r0 = q * DCH + (j - LSN + 1); c0 = 0; }
    int lenA = DCH - (r0 - q * DCH);
    int lenB = LSN - c0;
    int len = lenA < lenB ? lenA : lenB;
    int idx = r0 * LSN + c0;
    float acc = 0.f;
    #pragma unroll 8
    for (int s = 0; s < len; ++s) {
        acc += buf[idx];
        buf[idx] = acc;
        idx += LSN + 1;
    }
    Tt[(c0 - r0 + (R - 1)) * NCH + q] = acc;
}

// fused: local1 (17*64 = 1088 blocks) + local2 (17*32 = 544 blocks)
__global__ void fused_local_kernel() {
    int b = blockIdx.x;
    if (b < 17 * NCH1) {
        diag_local_body<NIN, NCH1, 0>(b % 17, b / 17);
    } else {
        b -= 17 * NCH1;
        diag_local_body<FCN, NCH2, 1>(b % 17, b / 17);
    }
}

// ---------------- register prefix-scan of chunk totals -> O[q][d] ----------------
// 64-thread blocks: one serial chain per SMSP, spread over all SMs.
template<int R, int NCH, int OB>
__device__ __forceinline__ void diag_offsets_body(int xblk) {
    const float* Tt = OB ? g_T2t : g_T1t;
    float (*O)[DMAX] = OB ? g_O2 : g_O1;
    int d = xblk * 64 + threadIdx.x;
    if (d >= R + LSN - 1) return;
    int dd = d - (R - 1);
    float t[NCH];
    const float4* p = reinterpret_cast<const float4*>(Tt + d * NCH);
    #pragma unroll
    for (int i = 0; i < NCH / 4; ++i) {
        float4 v = p[i];
        t[4 * i + 0] = v.x; t[4 * i + 1] = v.y;
        t[4 * i + 2] = v.z; t[4 * i + 3] = v.w;
    }
    float acc = 0.f;
    #pragma unroll
    for (int q = 0; q < NCH; ++q) {
        O[q][d] = acc;
        int rt = q * DCH, rb = rt + DCH - 1;
        if ((rt + dd < LSN) && (rb + dd >= 0)) acc += t[q];
    }
}

#define OB1 80   // ceil(5119/64)
#define OB2 72   // ceil(4607/64)

// fused: offsets1 + offsets2; block 0 also resets gemm64_1 counters
__global__ void fused_offsets_kernel() {
    int b = blockIdx.x;
    if (b == 0) g_cnt1[threadIdx.x] = 0u;          // 64 threads, 64 counters
    if (b < OB1) diag_offsets_body<NIN, NCH1, 0>(b);
    else         diag_offsets_body<FCN, NCH2, 1>(b - OB1);
}

// ---------------- apply GEMM body: OUT(64 x N) = A(64 x KT) @ C, K-split ----------------
// C reconstructed on the fly: C[r,c] = buf[r,c] + O[r/DCH][c - r + R-1]
template<int LAYER>
__device__ __forceinline__ void gemm64_body(int jblk, int kblk,
                                            float (*shA)[36], float (*shB)[68]) {
    constexpr int N  = (LAYER == 1) ? LSN : FCN;
    constexpr int KT = (LAYER == 1) ? NIN : LSN;
    constexpr int KC = (LAYER == 1) ? KC1 : KC2;
    constexpr int R  = (LAYER == 1) ? NIN : FCN;
    constexpr int BT = (LAYER == 1) ? 0 : 1;
    const float* A = (LAYER == 1) ? g_z1 : g_z2;
    const float* B = (LAYER == 1) ? g_buf1 : g_buf2;
    float (*O)[DMAX] = (LAYER == 1) ? g_O1 : g_O2;
    float* OUT = (LAYER == 1) ? g_y1p : g_y2p;
    int j0 = jblk * 64;
    int k0 = kblk * KC;
    int tid = threadIdx.x;
    int tx = tid & 15, ty = tid >> 4;
    float acc[4][4] = {};
    for (int ks = 0; ks < KC; ks += 32) {
        int kb = k0 + ks;
        #pragma unroll
        for (int it = 0; it < 2; ++it) {
            int e = it * 256 + tid;
            int bb = e >> 3, kk4 = (e & 7) * 4;
            *reinterpret_cast<float4*>(&shA[bb][kk4]) =
                *reinterpret_cast<const float4*>(A + bb * KT + kb + kk4);
        }
        if (BT == 0) {
            #pragma unroll
            for (int it = 0; it < 2; ++it) {
                int e = it * 256 + tid;
                int kk = e >> 4, jj4 = (e & 15) * 4;
                int kg = kb + kk;
                float4 v = *reinterpret_cast<const float4*>(B + kg * LSN + j0 + jj4);
                const float* Oq = O[kg >> 4];   // DCH = 16
                int d = (j0 + jj4) - kg + (R - 1);
                v.x += Oq[d]; v.y += Oq[d + 1]; v.z += Oq[d + 2]; v.w += Oq[d + 3];
                *reinterpret_cast<float4*>(&shB[kk][jj4]) = v;
            }
        } else {
            #pragma unroll
            for (int it = 0; it < 2; ++it) {
                int e = it * 256 + tid;
                int jj = e >> 3, kk4 = (e & 7) * 4;
                int jg = j0 + jj;
                float4 v = *reinterpret_cast<const float4*>(B + jg * KT + kb + kk4);
                const float* Oq = O[jg >> 4];
                int d = (kb + kk4) - jg + (R - 1);
                shB[kk4 + 0][jj] = v.x + Oq[d];
                shB[kk4 + 1][jj] = v.y + Oq[d + 1];
                shB[kk4 + 2][jj] = v.z + Oq[d + 2];
                shB[kk4 + 3][jj] = v.w + Oq[d + 3];
            }
        }
        __syncthreads();
        #pragma unroll
        for (int kk = 0; kk < 32; ++kk) {
            float a[4], b[4];
            #pragma unroll
            for (int u = 0; u < 4; ++u) a[u] = shA[ty * 4 + u][kk];
            #pragma unroll
            for (int v = 0; v < 4; ++v) b[v] = shB[kk][tx * 4 + v];
            #pragma unroll
            for (int u = 0; u < 4; ++u)
                #pragma unroll
                for (int v = 0; v < 4; ++v) acc[u][v] += a[u] * b[v];
        }
        __syncthreads();
    }
    #pragma unroll
    for (int u = 0; u < 4; ++u) {
        int bb = ty * 4 + u;
        float4 o = make_float4(acc[u][0], acc[u][1], acc[u][2], acc[u][3]);
        *reinterpret_cast<float4*>(OUT + kblk * (64 * N) + bb * N + j0 + tx * 4) = o;
    }
}

// gemm64_1 with fused per-jblk reduction (threadfence-reduction pattern).
// The last of the KCH1 blocks sharing a jblk reduces that 64x64 slab into z2.
__global__ void gemm64_1_kernel(const float* __restrict__ bias1) {
    __shared__ float shA[64][36];
    __shared__ float shB[32][68];
    int jblk = blockIdx.x & 63, kblk = blockIdx.x >> 6;
    gemm64_body<1>(jblk, kblk, shA, shB);
    __threadfence();
    __shared__ unsigned int isLast;
    if (threadIdx.x == 0)
        isLast = (atomicAdd(&g_cnt1[jblk], 1u) == KCH1 - 1u);
    __syncthreads();
    if (!isLast) return;
    // reduce 64 batch x 64 j slab (fixed summation order -> deterministic)
    int j0 = jblk * 64;
    int tid = threadIdx.x;
    #pragma unroll
    for (int e = 0; e < 4; ++e) {
        int lin = e * 256 + tid;
        int b = lin >> 4, jj4 = (lin & 15) * 4;
        int j = j0 + jj4;
        float4 s = *reinterpret_cast<const float4*>(&g_y1p[b * LSN + j]);
        #pragma unroll
        for (int c = 1; c < KCH1; ++c) {
            float4 p = *reinterpret_cast<const float4*>(&g_y1p[c * (BATN * LSN) + b * LSN + j]);
            s.x += p.x; s.y += p.y; s.z += p.z; s.w += p.w;
        }
        float4 da = *reinterpret_cast<const float4*>(&g_d[0][j]);
        float4 db = *reinterpret_cast<const float4*>(&g_d[6][j]);
        float4 bi = *reinterpret_cast<const float4*>(&bias1[j]);
        float4 o;
        o.x = fmaxf(da.x * s.x + bi.x, 0.f) * db.x;
        o.y = fmaxf(da.y * s.y + bi.y, 0.f) * db.y;
        o.z = fmaxf(da.z * s.z + bi.z, 0.f) * db.z;
        o.w = fmaxf(da.w * s.w + bi.w, 0.f) * db.w;
        *reinterpret_cast<float4*>(&g_z2[b * LSN + j]) = o;
    }
}

__global__ void gemm64_2_kernel() {
    __shared__ float shA[64][36];
    __shared__ float shB[32][68];
    gemm64_body<2>(blockIdx.x, blockIdx.y, shA, shB);
}

// ---------------- tail: reduce2 + logits fused (block per batch row) ----------------
__global__ void tail_kernel(const float* __restrict__ bias2, const float* __restrict__ W,
                            const float* __restrict__ bl, float* __restrict__ out) {
    __shared__ float h[FCN];
    int b = blockIdx.x;
    int t = threadIdx.x;
    for (int j = t; j < FCN; j += 256) {
        float s = 0.f;
        #pragma unroll
        for (int c = 0; c < KCH2; ++c) s += g_y2p[c * (BATN * FCN) + b * FCN + j];
        float v = g_d[4][j] * s + bias2[j];
        h[j] = v > 0.f ? v : 0.f;
    }
    __syncthreads();
    int warp = t >> 5, lane = t & 31;
    for (int c = warp; c < NCLS; c += 8) {
        const float* wrow = W + c * FCN;
        float s = 0.f;
        #pragma unroll 4
        for (int j = lane; j < FCN; j += 32) s += h[j] * wrow[j];
        #pragma unroll
        for (int off = 16; off; off >>= 1) s += __shfl_xor_sync(0xffffffffu, s, off);
        if (lane == 0) out[b * NCLS + c] = s + bl[c];
    }
}

// ---------------- launch ----------------
extern "C" void kernel_launch(void* const* d_in, const int* in_sizes, int n_in,
                              void* d_out, int out_size) {
    (void)in_sizes; (void)n_in; (void)out_size;
    const float* x      = (const float*)d_in[0];
    const float* G1     = (const float*)d_in[1];
    const float* H1     = (const float*)d_in[2];
    const float* sA1    = (const float*)d_in[3];
    const float* sB1    = (const float*)d_in[4];
    const float* bias1  = (const float*)d_in[5];
    const float* G2     = (const float*)d_in[6];
    const float* H2     = (const float*)d_in[7];
    const float* sA2    = (const float*)d_in[8];
    const float* sB2    = (const float*)d_in[9];
    const float* bias2  = (const float*)d_in[10];
    const float* W      = (const float*)d_in[11];
    const float* bl     = (const float*)d_in[12];
    float* out = (float*)d_out;

    // K1: cumprods + reciprocals + z1 = x*db1
    scan_kernel<<<4, 1024>>>(sA1, sB1, sA2, sB2, x);
    // K2: A1^T and A2 rank-r builds, fused
    fused_gemmA_kernel<<<1536, 256>>>(G1, H1, G2, H2);
    // K3: chunk-local diagonal cumsums of buf1 AND buf2, fused
    fused_local_kernel<<<17 * NCH1 + 17 * NCH2, 256>>>();
    // K4: offsets for both layers (64-thread blocks, all SMs) + counter reset
    fused_offsets_kernel<<<OB1 + OB2, 64>>>();
    // K5: Y1 partials (K-split 4) + fused per-jblk reduce1 epilogue
    gemm64_1_kernel<<<256, 256>>>(bias1);
    // K6: Y2 partials (K-split 16)
    gemm64_2_kernel<<<dim3(FCN / 64, KCH2), 256>>>();
    // K7: h2 = relu(da2*Y2 + bias2); logits = h2 @ W^T + b
    tail_kernel<<<BATN, 256>>>(bias2, W, bl, out);
}